// round 6
// baseline (speedup 1.0000x reference)
#include <cuda_runtime.h>
#include <cuda_bf16.h>
#include <cstdint>

#define S_LEN   2048
#define DMODEL  1024
#define BATCH   2
#define NHEADS  16
#define HDIM    64
#define QKV_LD  3072
#define NKTILES (S_LEN / 64)    // 32 key tiles per (b,h)
#define MROWS   (BATCH * S_LEN) // 4096
#define MB      (MROWS / 128)   // 32
#define KITERS  (DMODEL / 32)   // 32

__device__ float g_qkv[(size_t)BATCH * S_LEN * QKV_LD];
__device__ float g_ctx[(size_t)BATCH * S_LEN * DMODEL];
// attention K / V^T fragments
__device__ uint4 g_kfrag[(size_t)BATCH * NHEADS * NKTILES * 1024];
__device__ uint4 g_vfrag[(size_t)BATCH * NHEADS * NKTILES * 1024];
// GEMM operand fragments (bf16 hi/lo, MMA-fragment-major)
__device__ uint4 g_wqkv_frag[(size_t)(QKV_LD / 128) * KITERS * 1024];  // 24*32*1024
__device__ uint4 g_wout_frag[(size_t)(DMODEL / 128) * KITERS * 1024]; //  8*32*1024
__device__ uint4 g_atok_frag[(size_t)MB * KITERS * 1024];
__device__ uint4 g_actx_frag[(size_t)MB * KITERS * 1024];

// ---------------------------------------------------------------------------
__device__ __forceinline__ void mma_bf16(float* d, const uint32_t* a, const uint32_t* b) {
    asm volatile(
        "mma.sync.aligned.m16n8k16.row.col.f32.bf16.bf16.f32 "
        "{%0,%1,%2,%3}, {%4,%5,%6,%7}, {%8,%9}, {%0,%1,%2,%3};\n"
        : "+f"(d[0]), "+f"(d[1]), "+f"(d[2]), "+f"(d[3])
        : "r"(a[0]), "r"(a[1]), "r"(a[2]), "r"(a[3]), "r"(b[0]), "r"(b[1]));
}

__device__ __forceinline__ void split2(float x, __nv_bfloat16& hi, __nv_bfloat16& lo) {
    hi = __float2bfloat16(x);
    lo = __float2bfloat16(x - __bfloat162float(hi));
}

__device__ __forceinline__ void split_pack2(float x, float y, uint32_t& hi, uint32_t& lo) {
    __nv_bfloat16 xh, xl, yh, yl;
    split2(x, xh, xl); split2(y, yh, yl);
    __nv_bfloat162 h2 = __nv_bfloat162(xh, yh);
    __nv_bfloat162 l2 = __nv_bfloat162(xl, yl);
    hi = *(uint32_t*)&h2;  lo = *(uint32_t*)&l2;
}

__device__ __forceinline__ void cp_async16(void* smem_ptr, const void* gptr) {
    uint32_t sa = (uint32_t)__cvta_generic_to_shared(smem_ptr);
    asm volatile("cp.async.cg.shared.global [%0], [%1], 16;\n" :: "r"(sa), "l"(gptr));
}
__device__ __forceinline__ void cp_commit() {
    asm volatile("cp.async.commit_group;\n");
}
template <int N>
__device__ __forceinline__ void cp_wait() {
    asm volatile("cp.async.wait_group %0;\n" :: "n"(N));
}

// ---------------------------------------------------------------------------
// Presplit W [K=1024, N] -> B-fragment-major bf16 hi/lo.
// Chunk (nb, it) = 1024 uint4; slot s: lane=s&31, ni=(s>>5)&15, ks=s>>9.
// uint4 = {hi(Bk,Bk+1), hi(Bk+8,Bk+9), lo(..), lo(..)} at n = nb*128+ni*8+(lane>>2),
// k = it*32+ks*16+(lane&3)*2.
// ---------------------------------------------------------------------------
__global__ void __launch_bounds__(256) presplit_w_kernel(
    const float* __restrict__ W, uint4* __restrict__ out, int N)
{
    const int it = blockIdx.x;
    const int nb = blockIdx.y;
    uint4* chunk = out + ((size_t)nb * KITERS + it) * 1024;
#pragma unroll
    for (int i = 0; i < 4; i++) {
        const int s    = threadIdx.x + i * 256;
        const int lane = s & 31;
        const int ni   = (s >> 5) & 15;
        const int ks   = s >> 9;
        const int n = nb * 128 + ni * 8 + (lane >> 2);
        const int k = it * 32 + ks * 16 + (lane & 3) * 2;
        const float b0 = W[(size_t)k * N + n];
        const float b1 = W[(size_t)(k + 1) * N + n];
        const float b2 = W[(size_t)(k + 8) * N + n];
        const float b3 = W[(size_t)(k + 9) * N + n];
        uint32_t h0, l0, h1, l1;
        split_pack2(b0, b1, h0, l0);
        split_pack2(b2, b3, h1, l1);
        chunk[s] = make_uint4(h0, h1, l0, l1);
    }
}

// ---------------------------------------------------------------------------
// Presplit A [4096, 1024] -> A-fragment-major bf16 hi/lo.
// Chunk (mb, it) = 1024 uint4: hi at slot s (0..511), lo at 512+s.
// slot s: lane=s&31, mt=(s>>5)&7, ks=s>>8.
// hi uint4 = {A[m][k,k+1], A[m+8][k,k+1], A[m][k+8,k+9], A[m+8][k+8,k+9]}
// ---------------------------------------------------------------------------
__global__ void __launch_bounds__(256) presplit_a_kernel(
    const float* __restrict__ A, uint4* __restrict__ out)
{
    const int it = blockIdx.x;
    const int mb = blockIdx.y;
    uint4* chunk = out + ((size_t)mb * KITERS + it) * 1024;
#pragma unroll
    for (int i = 0; i < 2; i++) {
        const int s    = threadIdx.x + i * 256;
        const int lane = s & 31;
        const int mt   = (s >> 5) & 7;
        const int ks   = s >> 8;
        const int m = mb * 128 + mt * 16 + (lane >> 2);
        const int k = it * 32 + ks * 16 + (lane & 3) * 2;
        const float2 r0 = *(const float2*)&A[(size_t)m * DMODEL + k];
        const float2 r1 = *(const float2*)&A[(size_t)(m + 8) * DMODEL + k];
        const float2 r2 = *(const float2*)&A[(size_t)m * DMODEL + k + 8];
        const float2 r3 = *(const float2*)&A[(size_t)(m + 8) * DMODEL + k + 8];
        uint32_t h0, l0, h1, l1, h2, l2, h3, l3;
        split_pack2(r0.x, r0.y, h0, l0);
        split_pack2(r1.x, r1.y, h1, l1);
        split_pack2(r2.x, r2.y, h2, l2);
        split_pack2(r3.x, r3.y, h3, l3);
        chunk[s]       = make_uint4(h0, h1, h2, h3);
        chunk[512 + s] = make_uint4(l0, l1, l2, l3);
    }
}

// ---------------------------------------------------------------------------
// Fragment GEMM: C[4096, N] = A @ W + bias, from presplit fragments.
// BM=BN=128, BK=32. 8 warps, warp tile 64x32. cp.async double-buffered.
// ---------------------------------------------------------------------------
__global__ void __launch_bounds__(256) gemm_frag_kernel(
    const uint4* __restrict__ Afrag, const uint4* __restrict__ Bfrag,
    const float* __restrict__ bias, float* __restrict__ C, int N)
{
    extern __shared__ uint4 dyn[];
    // sA: [2][1024] (hi 512 + lo 512), sB: [2][1024]

    const int tid    = threadIdx.x;
    const int lane   = tid & 31;
    const int wid    = tid >> 5;
    const int nb     = blockIdx.x;
    const int mb     = blockIdx.y;
    const int warp_m = (wid >> 2);   // 0/1 -> rows 0/64
    const int warp_n = (wid & 3);    // 0..3 -> cols *32

    const uint4* Ab = Afrag + ((size_t)mb * KITERS) * 1024;
    const uint4* Bb = Bfrag + ((size_t)nb * KITERS) * 1024;

    float acc[4][4][4];
#pragma unroll
    for (int mi = 0; mi < 4; mi++)
#pragma unroll
        for (int ni = 0; ni < 4; ni++)
#pragma unroll
            for (int r = 0; r < 4; r++) acc[mi][ni][r] = 0.f;

    // prologue: stage chunk 0
#pragma unroll
    for (int i = 0; i < 4; i++) {
        const int idx = tid + i * 256;
        cp_async16(&dyn[idx], Ab + idx);
        cp_async16(&dyn[2048 + idx], Bb + idx);
    }
    cp_commit();

    for (int it = 0; it < KITERS; it++) {
        const int buf = it & 1;
        if (it + 1 < KITERS) {
            const int nbuf = (it + 1) & 1;
            const uint4* sa = Ab + (size_t)(it + 1) * 1024;
            const uint4* sb = Bb + (size_t)(it + 1) * 1024;
#pragma unroll
            for (int i = 0; i < 4; i++) {
                const int idx = tid + i * 256;
                cp_async16(&dyn[nbuf * 1024 + idx], sa + idx);
                cp_async16(&dyn[2048 + nbuf * 1024 + idx], sb + idx);
            }
            cp_commit();
            cp_wait<1>();
        } else {
            cp_wait<0>();
        }
        __syncthreads();

        const uint4* bA = dyn + buf * 1024;
        const uint4* bB = dyn + 2048 + buf * 1024;

#pragma unroll
        for (int ks = 0; ks < 2; ks++) {
            uint4 ah[4], al[4], bb[4];
#pragma unroll
            for (int mi = 0; mi < 4; mi++) {
                const int mt   = warp_m * 4 + mi;
                const int slot = (ks * 8 + mt) * 32 + lane;
                ah[mi] = bA[slot];
                al[mi] = bA[512 + slot];
            }
#pragma unroll
            for (int ni = 0; ni < 4; ni++) {
                const int n8   = warp_n * 4 + ni;
                const int slot = (ks * 16 + n8) * 32 + lane;
                bb[ni] = bB[slot];
            }
#pragma unroll
            for (int mi = 0; mi < 4; mi++) {
                const uint32_t* ahp = (const uint32_t*)&ah[mi];
                const uint32_t* alp = (const uint32_t*)&al[mi];
#pragma unroll
                for (int ni = 0; ni < 4; ni++) {
                    uint32_t bfr[2] = {bb[ni].x, bb[ni].y};
                    uint32_t bfl[2] = {bb[ni].z, bb[ni].w};
                    mma_bf16(acc[mi][ni], ahp, bfr);
                    mma_bf16(acc[mi][ni], ahp, bfl);
                    mma_bf16(acc[mi][ni], alp, bfr);
                }
            }
        }
        __syncthreads();
    }

    // epilogue
    const int bm = mb * 128;
    const int bn = nb * 128;
#pragma unroll
    for (int mi = 0; mi < 4; mi++) {
        const int row = bm + warp_m * 64 + mi * 16 + (lane >> 2);
#pragma unroll
        for (int ni = 0; ni < 4; ni++) {
            const int col = bn + warp_n * 32 + ni * 8 + (lane & 3) * 2;
            const float2 bv = *(const float2*)&bias[col];
            float2 o0, o1;
            o0.x = acc[mi][ni][0] + bv.x;  o0.y = acc[mi][ni][1] + bv.y;
            o1.x = acc[mi][ni][2] + bv.x;  o1.y = acc[mi][ni][3] + bv.y;
            *(float2*)&C[(size_t)row * N + col]       = o0;
            *(float2*)&C[(size_t)(row + 8) * N + col] = o1;
        }
    }
}

// ---------------------------------------------------------------------------
// ns overwrite (unchanged)
// ---------------------------------------------------------------------------
__global__ void __launch_bounds__(256) ns_kernel(
    const float* __restrict__ tokens, const int* __restrict__ seqc,
    const float* __restrict__ Wq, const float* __restrict__ bq,
    const float* __restrict__ Wk, const float* __restrict__ bk,
    const float* __restrict__ Wv, const float* __restrict__ bv)
{
    __shared__ float st[DMODEL];
    const int bxid = blockIdx.x;
    const int mat = bxid >> 4;
    const int b   = (bxid >> 3) & 1;
    const int n   = bxid & 7;

    const int pos = *seqc;
    const int row = pos + n;
    if (pos < 0 || row < 0 || row >= S_LEN) return;

    const float* W; const float* bb;
    if (mat == 0)      { W = Wq; bb = bq; }
    else if (mat == 1) { W = Wk; bb = bk; }
    else               { W = Wv; bb = bv; }
    W  += (size_t)n * DMODEL * DMODEL;
    bb += n * DMODEL;

    const float* trow = tokens + ((size_t)b * S_LEN + row) * DMODEL;
    const int tid = threadIdx.x;
    *(float4*)&st[tid * 4] = *(const float4*)&trow[tid * 4];
    __syncthreads();

    float acc[4];
#pragma unroll
    for (int j = 0; j < 4; j++) acc[j] = bb[tid + 256 * j];

    for (int d = 0; d < DMODEL; d++) {
        const float td = st[d];
        const float* wr = W + (size_t)d * DMODEL;
#pragma unroll
        for (int j = 0; j < 4; j++) acc[j] += td * wr[tid + 256 * j];
    }

    float* out = g_qkv + ((size_t)b * S_LEN + row) * QKV_LD + mat * DMODEL;
#pragma unroll
    for (int j = 0; j < 4; j++) out[tid + 256 * j] = acc[j];
}

// ---------------------------------------------------------------------------
// Presplit K and V^T for attention (unchanged from R5)
// ---------------------------------------------------------------------------
__global__ void __launch_bounds__(256) presplit_kernel()
{
    __shared__ float stage[64][68];
    const int tile = blockIdx.x;
    const int bh   = blockIdx.y;
    const int b    = bh >> 4;
    const int h    = bh & 15;
    const int tid  = threadIdx.x;

    const float* kb = g_qkv + ((size_t)b * S_LEN + tile * 64) * QKV_LD + DMODEL + h * HDIM;
    const float* vb = kb + DMODEL;
    const size_t obase = ((size_t)bh * NKTILES + tile) << 10;

#pragma unroll
    for (int i = 0; i < 4; i++) {
        const int f = tid + i * 256;
        *(float4*)&stage[f >> 4][(f & 15) * 4] =
            *(const float4*)&kb[(size_t)(f >> 4) * QKV_LD + (f & 15) * 4];
    }
    __syncthreads();
#pragma unroll
    for (int i = 0; i < 4; i++) {
        const int s = tid + i * 256;
        const int g = s >> 5, l = s & 31;
        const int key = (g >> 2) * 8 + (l >> 2);
        const int c   = (g & 3) * 16 + (l & 3) * 2;
        __nv_bfloat16 h0,l0,h1,l1,h2,l2,h3,l3;
        split2(stage[key][c],     h0, l0);
        split2(stage[key][c + 1], h1, l1);
        split2(stage[key][c + 8], h2, l2);
        split2(stage[key][c + 9], h3, l3);
        __nv_bfloat162 w0(h0,h1), w1(h2,h3), w2(l0,l1), w3(l2,l3);
        g_kfrag[obase + s] = make_uint4(*(uint32_t*)&w0, *(uint32_t*)&w1,
                                        *(uint32_t*)&w2, *(uint32_t*)&w3);
    }
    __syncthreads();

#pragma unroll
    for (int i = 0; i < 4; i++) {
        const int f = tid + i * 256;
        *(float4*)&stage[f >> 4][(f & 15) * 4] =
            *(const float4*)&vb[(size_t)(f >> 4) * QKV_LD + (f & 15) * 4];
    }
    __syncthreads();
#pragma unroll
    for (int i = 0; i < 4; i++) {
        const int s = tid + i * 256;
        const int g = s >> 5, l = s & 31;
        const int d  = (g >> 2) * 8 + (l >> 2);
        const int kk = (g & 3) * 16 + (l & 3) * 2;
        __nv_bfloat16 h0,l0,h1,l1,h2,l2,h3,l3;
        split2(stage[kk][d],     h0, l0);
        split2(stage[kk + 1][d], h1, l1);
        split2(stage[kk + 8][d], h2, l2);
        split2(stage[kk + 9][d], h3, l3);
        __nv_bfloat162 w0(h0,h1), w1(h2,h3), w2(l0,l1), w3(l2,l3);
        g_vfrag[obase + s] = make_uint4(*(uint32_t*)&w0, *(uint32_t*)&w1,
                                        *(uint32_t*)&w2, *(uint32_t*)&w3);
    }
}

// ---------------------------------------------------------------------------
// Tensor-core flash attention (unchanged from R5)
// ---------------------------------------------------------------------------
__global__ void __launch_bounds__(256) attn_tc_kernel(
    const unsigned int* __restrict__ mask)
{
    extern __shared__ uint4 dyn[];
    uint4*    sK    = dyn;
    uint4*    sV    = dyn + 2048;
    uint32_t* sMask = (uint32_t*)(dyn + 4096);

    const int tid  = threadIdx.x;
    const int w    = tid >> 5;
    const int lane = tid & 31;
    const int bxr  = (S_LEN / 128 - 1) - blockIdx.x;
    const int bh   = blockIdx.y;
    const int b    = bh >> 4;
    const int h    = bh & 15;
    const int r0   = bxr * 128;

    const float* qb = g_qkv + ((size_t)b * S_LEN) * QKV_LD + h * HDIM;
    const unsigned int* mb = mask + b * S_LEN;
    const uint4* kfb = g_kfrag + ((size_t)bh * NKTILES << 10);
    const uint4* vfb = g_vfrag + ((size_t)bh * NKTILES << 10);

    const int ntiles = (r0 + 128) >> 6;

    uint32_t qh[4][4], ql[4][4];
    {
        const int rlo = r0 + w * 16 + (lane >> 2);
        const float* q0 = qb + (size_t)rlo * QKV_LD;
        const float* q1 = qb + (size_t)(rlo + 8) * QKV_LD;
#pragma unroll
        for (int ks = 0; ks < 4; ks++) {
            const int c = ks * 16 + (lane & 3) * 2;
            float2 x0 = *(const float2*)&q0[c];
            float2 x1 = *(const float2*)&q1[c];
            float2 x2 = *(const float2*)&q0[c + 8];
            float2 x3 = *(const float2*)&q1[c + 8];
            split_pack2(x0.x * 0.125f, x0.y * 0.125f, qh[ks][0], ql[ks][0]);
            split_pack2(x1.x * 0.125f, x1.y * 0.125f, qh[ks][1], ql[ks][1]);
            split_pack2(x2.x * 0.125f, x2.y * 0.125f, qh[ks][2], ql[ks][2]);
            split_pack2(x3.x * 0.125f, x3.y * 0.125f, qh[ks][3], ql[ks][3]);
        }
    }

    float m_i[2] = {-1e30f, -1e30f};
    float l_i[2] = {0.f, 0.f};
    float o_acc[8][4];
#pragma unroll
    for (int dt = 0; dt < 8; dt++)
#pragma unroll
        for (int r = 0; r < 4; r++) o_acc[dt][r] = 0.f;

    const int q0g = r0 + w * 16 + (lane >> 2);

    {
#pragma unroll
        for (int i = 0; i < 4; i++) {
            const int idx = tid + i * 256;
            cp_async16(&sK[idx], kfb + idx);
            cp_async16(&sV[idx], vfb + idx);
        }
        if (tid < 16) cp_async16(&sMask[tid * 4], mb + tid * 4);
        cp_commit();
    }

    for (int t = 0; t < ntiles; t++) {
        const int buf = t & 1;
        if (t + 1 < ntiles) {
            const int nb = (t + 1) & 1;
            const uint4* srcK = kfb + ((size_t)(t + 1) << 10);
            const uint4* srcV = vfb + ((size_t)(t + 1) << 10);
#pragma unroll
            for (int i = 0; i < 4; i++) {
                const int idx = tid + i * 256;
                cp_async16(&sK[nb * 1024 + idx], srcK + idx);
                cp_async16(&sV[nb * 1024 + idx], srcV + idx);
            }
            if (tid < 16) cp_async16(&sMask[nb * 64 + tid * 4], mb + (t + 1) * 64 + tid * 4);
            cp_commit();
            cp_wait<1>();
        } else {
            cp_wait<0>();
        }
        __syncthreads();

        const int k0 = t << 6;
        const uint4* bK = sK + buf * 1024;
        const uint4* bV = sV + buf * 1024;
        const uint32_t* bM = sMask + buf * 64;

        float s[8][4];
#pragma unroll
        for (int nt = 0; nt < 8; nt++)
#pragma unroll
            for (int r = 0; r < 4; r++) s[nt][r] = 0.f;

#pragma unroll
        for (int ks = 0; ks < 4; ks++) {
#pragma unroll
            for (int nt = 0; nt < 8; nt++) {
                const uint4 v = bK[(nt * 4 + ks) * 32 + lane];
                uint32_t bfr[2] = {v.x, v.y};
                uint32_t bfl[2] = {v.z, v.w};
                mma_bf16(s[nt], qh[ks], bfr);
                mma_bf16(s[nt], qh[ks], bfl);
                mma_bf16(s[nt], ql[ks], bfr);
            }
        }

#pragma unroll
        for (int row = 0; row < 2; row++) {
            const int qg = q0g + row * 8;
            float mx = -1e30f;
#pragma unroll
            for (int nt = 0; nt < 8; nt++)
#pragma unroll
                for (int c = 0; c < 2; c++) {
                    const int idx = row * 2 + c;
                    const int kl  = nt * 8 + (lane & 3) * 2 + c;
                    const bool ok = (bM[kl] != 0u) && (k0 + kl <= qg);
                    s[nt][idx] = ok ? s[nt][idx] : -1e9f;
                    mx = fmaxf(mx, s[nt][idx]);
                }
            mx = fmaxf(mx, __shfl_xor_sync(0xffffffffu, mx, 1));
            mx = fmaxf(mx, __shfl_xor_sync(0xffffffffu, mx, 2));
            const float mnew = fmaxf(m_i[row], mx);
            const float corr = __expf(m_i[row] - mnew);
            float sum = 0.f;
#pragma unroll
            for (int nt = 0; nt < 8; nt++)
#pragma unroll
                for (int c = 0; c < 2; c++) {
                    const int idx = row * 2 + c;
                    const float p = __expf(s[nt][idx] - mnew);
                    s[nt][idx] = p;
                    sum += p;
                }
            sum += __shfl_xor_sync(0xffffffffu, sum, 1);
            sum += __shfl_xor_sync(0xffffffffu, sum, 2);
            l_i[row] = l_i[row] * corr + sum;
            m_i[row] = mnew;
#pragma unroll
            for (int dt = 0; dt < 8; dt++) {
                o_acc[dt][row * 2 + 0] *= corr;
                o_acc[dt][row * 2 + 1] *= corr;
            }
        }

#pragma unroll
        for (int ks2 = 0; ks2 < 4; ks2++) {
            uint32_t pah[4], pal[4];
            split_pack2(s[ks2*2][0],   s[ks2*2][1],   pah[0], pal[0]);
            split_pack2(s[ks2*2][2],   s[ks2*2][3],   pah[1], pal[1]);
            split_pack2(s[ks2*2+1][0], s[ks2*2+1][1], pah[2], pal[2]);
            split_pack2(s[ks2*2+1][2], s[ks2*2+1][3], pah[3], pal[3]);
#pragma unroll
            for (int dt = 0; dt < 8; dt++) {
                const uint4 v = bV[(dt * 4 + ks2) * 32 + lane];
                uint32_t bfr[2] = {v.x, v.y};
                uint32_t bfl[2] = {v.z, v.w};
                mma_bf16(o_acc[dt], pah, bfr);
                mma_bf16(o_acc[dt], pah, bfl);
                mma_bf16(o_acc[dt], pal, bfr);
            }
        }
        __syncthreads();
    }

    const float inv0 = 1.f / l_i[0];
    const float inv1 = 1.f / l_i[1];
    float* ob = g_ctx + ((size_t)b * S_LEN) * DMODEL + h * HDIM;
#pragma unroll
    for (int dt = 0; dt < 8; dt++) {
        const int col = dt * 8 + (lane & 3) * 2;
        float2 o0, o1;
        o0.x = o_acc[dt][0] * inv0;  o0.y = o_acc[dt][1] * inv0;
        o1.x = o_acc[dt][2] * inv1;  o1.y = o_acc[dt][3] * inv1;
        *(float2*)&ob[(size_t)q0g * DMODEL + col]       = o0;
        *(float2*)&ob[(size_t)(q0g + 8) * DMODEL + col] = o1;
    }
}

// ---------------------------------------------------------------------------
extern "C" void kernel_launch(void* const* d_in, const int* in_sizes, int n_in,
                              void* d_out, int out_size)
{
    const float*        tokens = (const float*)d_in[0];
    const unsigned int* mask   = (const unsigned int*)d_in[1];
    const int*          seqc   = (const int*)d_in[2];
    const float*        W_qkv  = (const float*)d_in[3];
    const float*        b_qkv  = (const float*)d_in[4];
    const float*        Wq     = (const float*)d_in[5];
    const float*        bq     = (const float*)d_in[6];
    const float*        Wk     = (const float*)d_in[7];
    const float*        bk     = (const float*)d_in[8];
    const float*        Wv     = (const float*)d_in[9];
    const float*        bv     = (const float*)d_in[10];
    const float*        W_out  = (const float*)d_in[11];
    const float*        b_out  = (const float*)d_in[12];
    float*              out    = (float*)d_out;

    float* qkv = nullptr;
    float* ctx = nullptr;
    uint4 *wqkvF = nullptr, *woutF = nullptr, *atokF = nullptr, *actxF = nullptr;
    cudaGetSymbolAddress((void**)&qkv, g_qkv);
    cudaGetSymbolAddress((void**)&ctx, g_ctx);
    cudaGetSymbolAddress((void**)&wqkvF, g_wqkv_frag);
    cudaGetSymbolAddress((void**)&woutF, g_wout_frag);
    cudaGetSymbolAddress((void**)&atokF, g_atok_frag);
    cudaGetSymbolAddress((void**)&actxF, g_actx_frag);

    cudaFuncSetAttribute(attn_tc_kernel,
                         cudaFuncAttributeMaxDynamicSharedMemorySize, 66048);
    cudaFuncSetAttribute(gemm_frag_kernel,
                         cudaFuncAttributeMaxDynamicSharedMemorySize, 65536);

    // presplit weights + tokens
    dim3 gw1(KITERS, QKV_LD / 128);
    presplit_w_kernel<<<gw1, 256>>>(W_qkv, wqkvF, QKV_LD);
    dim3 gw2(KITERS, DMODEL / 128);
    presplit_w_kernel<<<gw2, 256>>>(W_out, woutF, DMODEL);
    dim3 ga(KITERS, MB);
    presplit_a_kernel<<<ga, 256>>>(tokens, atokF);

    // 1) QKV projection
    dim3 g1(QKV_LD / 128, MB);
    gemm_frag_kernel<<<g1, 256, 65536>>>(atokF, wqkvF, b_qkv, qkv, QKV_LD);

    // 2) ns overwrites
    ns_kernel<<<48, 256>>>(tokens, seqc, Wq, bq, Wk, bk, Wv, bv);

    // 3) K/V presplit for attention
    dim3 gp(NKTILES, BATCH * NHEADS);
    presplit_kernel<<<gp, 256>>>();

    // 4) attention
    dim3 g2(S_LEN / 128, BATCH * NHEADS);
    attn_tc_kernel<<<g2, 256, 66048>>>(mask);

    // 5) presplit ctx + output projection
    presplit_a_kernel<<<ga, 256>>>(ctx, actxF);
    dim3 g3(DMODEL / 128, MB);
    gemm_frag_kernel<<<g3, 256, 65536>>>(actxF, woutF, b_out, out, DMODEL);
}

// round 8
// speedup vs baseline: 1.4407x; 1.4407x over previous
#include <cuda_runtime.h>
#include <cuda_fp16.h>
#include <cstdint>

#define S_LEN   2048
#define DMODEL  1024
#define BATCH   2
#define NHEADS  16
#define HDIM    64
#define QKV_LD  3072
#define NKTILES (S_LEN / 64)

__device__ float g_qkv[(size_t)BATCH * S_LEN * QKV_LD];
__device__ float g_ctx[(size_t)BATCH * S_LEN * DMODEL];
// K / V^T fragments, fp16 hi/lo: [bh][tile][group(32)][lane(32)] uint4
__device__ uint4 g_kfrag[(size_t)BATCH * NHEADS * NKTILES * 1024];
__device__ uint4 g_vfrag[(size_t)BATCH * NHEADS * NKTILES * 1024];

// ---------------------------------------------------------------------------
__device__ __forceinline__ void mma_f16(float* d, const uint32_t* a, const uint32_t* b) {
    asm volatile(
        "mma.sync.aligned.m16n8k16.row.col.f32.f16.f16.f32 "
        "{%0,%1,%2,%3}, {%4,%5,%6,%7}, {%8,%9}, {%0,%1,%2,%3};\n"
        : "+f"(d[0]), "+f"(d[1]), "+f"(d[2]), "+f"(d[3])
        : "r"(a[0]), "r"(a[1]), "r"(a[2]), "r"(a[3]), "r"(b[0]), "r"(b[1]));
}

__device__ __forceinline__ void split2h(float x, __half& hi, __half& lo) {
    hi = __float2half_rn(x);
    lo = __float2half_rn(x - __half2float(hi));
}

__device__ __forceinline__ uint32_t pack2h(float x, float y) {
    __half2 h = __floats2half2_rn(x, y);
    return *(uint32_t*)&h;
}

__device__ __forceinline__ void cp_async16(void* smem_ptr, const void* gptr) {
    uint32_t sa = (uint32_t)__cvta_generic_to_shared(smem_ptr);
    asm volatile("cp.async.cg.shared.global [%0], [%1], 16;\n" :: "r"(sa), "l"(gptr));
}
__device__ __forceinline__ void cp_commit() {
    asm volatile("cp.async.commit_group;\n");
}
template <int N>
__device__ __forceinline__ void cp_wait() {
    asm volatile("cp.async.wait_group %0;\n" :: "n"(N));
}

// ---------------------------------------------------------------------------
// fp16x2 compensated GEMM: C[M,N] = A[M,K] @ B[K,N] + bias[N]
// A rounded to fp16 (2^-11 rel); B split hi/lo (~fp22). 2 MMAs per product.
// BM=BN=128, BK=32, 256 threads (8 warps), warp tile 64x32 via m16n8k16.
// ---------------------------------------------------------------------------
__global__ void __launch_bounds__(256) gemm_f16x2_kernel(
    const float* __restrict__ A, const float* __restrict__ B,
    const float* __restrict__ bias, float* __restrict__ C,
    int M, int N, int K)
{
    __shared__ __half sA[128][40];     // [m][k], pad 8
    __shared__ __half sBhi[32][136];   // [k][n], pad 8
    __shared__ __half sBlo[32][136];

    const int tid    = threadIdx.x;
    const int lane   = tid & 31;
    const int wid    = tid >> 5;
    const int bm     = blockIdx.y * 128;
    const int bn     = blockIdx.x * 128;
    const int warp_m = (wid >> 2) * 64;
    const int warp_n = (wid & 3) * 32;

    float acc[4][4][4];
#pragma unroll
    for (int mi = 0; mi < 4; mi++)
#pragma unroll
        for (int ni = 0; ni < 4; ni++)
#pragma unroll
            for (int r = 0; r < 4; r++) acc[mi][ni][r] = 0.f;

    float4 av[4], bv[4];
#pragma unroll
    for (int i = 0; i < 4; i++) {
        const int f = tid + i * 256;
        av[i] = *(const float4*)&A[(size_t)(bm + (f >> 3)) * K + (f & 7) * 4];
        bv[i] = *(const float4*)&B[(size_t)(f >> 5) * N + bn + (f & 31) * 4];
    }

    for (int k0 = 0; k0 < K; k0 += 32) {
        __syncthreads();
#pragma unroll
        for (int i = 0; i < 4; i++) {
            const int f    = tid + i * 256;
            const int arow = f >> 3, acol = (f & 7) * 4;
            const int krow = f >> 5, ncol = (f & 31) * 4;
            sA[arow][acol + 0] = __float2half_rn(av[i].x);
            sA[arow][acol + 1] = __float2half_rn(av[i].y);
            sA[arow][acol + 2] = __float2half_rn(av[i].z);
            sA[arow][acol + 3] = __float2half_rn(av[i].w);
            __half h0, l0, h1, l1, h2, l2, h3, l3;
            split2h(bv[i].x, h0, l0); split2h(bv[i].y, h1, l1);
            split2h(bv[i].z, h2, l2); split2h(bv[i].w, h3, l3);
            sBhi[krow][ncol+0] = h0; sBhi[krow][ncol+1] = h1;
            sBhi[krow][ncol+2] = h2; sBhi[krow][ncol+3] = h3;
            sBlo[krow][ncol+0] = l0; sBlo[krow][ncol+1] = l1;
            sBlo[krow][ncol+2] = l2; sBlo[krow][ncol+3] = l3;
        }
        __syncthreads();

        if (k0 + 32 < K) {
            const int kn = k0 + 32;
#pragma unroll
            for (int i = 0; i < 4; i++) {
                const int f = tid + i * 256;
                av[i] = *(const float4*)&A[(size_t)(bm + (f >> 3)) * K + kn + (f & 7) * 4];
                bv[i] = *(const float4*)&B[(size_t)(kn + (f >> 5)) * N + bn + (f & 31) * 4];
            }
        }

#pragma unroll
        for (int ks = 0; ks < 2; ks++) {
            const int kb = ks * 16;
            uint32_t ah[4][4], bh[4][2], bl[4][2];
#pragma unroll
            for (int mi = 0; mi < 4; mi++) {
                const int m = warp_m + mi * 16 + (lane >> 2);
                const int c = kb + (lane & 3) * 2;
                ah[mi][0] = *(const uint32_t*)&sA[m][c];
                ah[mi][1] = *(const uint32_t*)&sA[m + 8][c];
                ah[mi][2] = *(const uint32_t*)&sA[m][c + 8];
                ah[mi][3] = *(const uint32_t*)&sA[m + 8][c + 8];
            }
#pragma unroll
            for (int ni = 0; ni < 4; ni++) {
                const int n  = warp_n + ni * 8 + (lane >> 2);
                const int kk = kb + (lane & 3) * 2;
                uint32_t u0, u1;
                u0 = *(const unsigned short*)&sBhi[kk][n];
                u1 = *(const unsigned short*)&sBhi[kk + 1][n];
                bh[ni][0] = u0 | (u1 << 16);
                u0 = *(const unsigned short*)&sBhi[kk + 8][n];
                u1 = *(const unsigned short*)&sBhi[kk + 9][n];
                bh[ni][1] = u0 | (u1 << 16);
                u0 = *(const unsigned short*)&sBlo[kk][n];
                u1 = *(const unsigned short*)&sBlo[kk + 1][n];
                bl[ni][0] = u0 | (u1 << 16);
                u0 = *(const unsigned short*)&sBlo[kk + 8][n];
                u1 = *(const unsigned short*)&sBlo[kk + 9][n];
                bl[ni][1] = u0 | (u1 << 16);
            }
#pragma unroll
            for (int mi = 0; mi < 4; mi++)
#pragma unroll
                for (int ni = 0; ni < 4; ni++) {
                    mma_f16(acc[mi][ni], ah[mi], bh[ni]);
                    mma_f16(acc[mi][ni], ah[mi], bl[ni]);
                }
        }
    }

#pragma unroll
    for (int mi = 0; mi < 4; mi++) {
        const int row = bm + warp_m + mi * 16 + (lane >> 2);
#pragma unroll
        for (int ni = 0; ni < 4; ni++) {
            const int col = bn + warp_n + ni * 8 + (lane & 3) * 2;
            const float2 bb = *(const float2*)&bias[col];
            float2 o0, o1;
            o0.x = acc[mi][ni][0] + bb.x;  o0.y = acc[mi][ni][1] + bb.y;
            o1.x = acc[mi][ni][2] + bb.x;  o1.y = acc[mi][ni][3] + bb.y;
            *(float2*)&C[(size_t)row * N + col]       = o0;
            *(float2*)&C[(size_t)(row + 8) * N + col] = o1;
        }
    }
}

// ---------------------------------------------------------------------------
// ns overwrite (proven R5 version)
// ---------------------------------------------------------------------------
__global__ void __launch_bounds__(256) ns_kernel(
    const float* __restrict__ tokens, const int* __restrict__ seqc,
    const float* __restrict__ Wq, const float* __restrict__ bq,
    const float* __restrict__ Wk, const float* __restrict__ bk,
    const float* __restrict__ Wv, const float* __restrict__ bv)
{
    __shared__ float st[DMODEL];
    const int bxid = blockIdx.x;
    const int mat = bxid >> 4;
    const int b   = (bxid >> 3) & 1;
    const int n   = bxid & 7;

    const int pos = *seqc;
    const int row = pos + n;
    if (pos < 0 || row < 0 || row >= S_LEN) return;

    const float* W; const float* bb;
    if (mat == 0)      { W = Wq; bb = bq; }
    else if (mat == 1) { W = Wk; bb = bk; }
    else               { W = Wv; bb = bv; }
    W  += (size_t)n * DMODEL * DMODEL;
    bb += n * DMODEL;

    const float* trow = tokens + ((size_t)b * S_LEN + row) * DMODEL;
    const int tid = threadIdx.x;
    *(float4*)&st[tid * 4] = *(const float4*)&trow[tid * 4];
    __syncthreads();

    float acc[4];
#pragma unroll
    for (int j = 0; j < 4; j++) acc[j] = bb[tid + 256 * j];

    for (int d = 0; d < DMODEL; d++) {
        const float td = st[d];
        const float* wr = W + (size_t)d * DMODEL;
#pragma unroll
        for (int j = 0; j < 4; j++) acc[j] += td * wr[tid + 256 * j];
    }

    float* out = g_qkv + ((size_t)b * S_LEN + row) * QKV_LD + mat * DMODEL;
#pragma unroll
    for (int j = 0; j < 4; j++) out[tid + 256 * j] = acc[j];
}

// ---------------------------------------------------------------------------
// Presplit K and V^T -> fragment-major fp16 hi/lo (R5 layout, fp16)
// ---------------------------------------------------------------------------
__global__ void __launch_bounds__(256) presplit_kernel()
{
    __shared__ float stage[64][68];
    const int tile = blockIdx.x;
    const int bh   = blockIdx.y;
    const int b    = bh >> 4;
    const int h    = bh & 15;
    const int tid  = threadIdx.x;

    const float* kb = g_qkv + ((size_t)b * S_LEN + tile * 64) * QKV_LD + DMODEL + h * HDIM;
    const float* vb = kb + DMODEL;
    const size_t obase = ((size_t)bh * NKTILES + tile) << 10;

#pragma unroll
    for (int i = 0; i < 4; i++) {
        const int f = tid + i * 256;
        *(float4*)&stage[f >> 4][(f & 15) * 4] =
            *(const float4*)&kb[(size_t)(f >> 4) * QKV_LD + (f & 15) * 4];
    }
    __syncthreads();
#pragma unroll
    for (int i = 0; i < 4; i++) {
        const int s = tid + i * 256;
        const int g = s >> 5, l = s & 31;
        const int key = (g >> 2) * 8 + (l >> 2);
        const int c   = (g & 3) * 16 + (l & 3) * 2;
        __half h0,l0,h1,l1,h2,l2,h3,l3;
        split2h(stage[key][c],     h0, l0);
        split2h(stage[key][c + 1], h1, l1);
        split2h(stage[key][c + 8], h2, l2);
        split2h(stage[key][c + 9], h3, l3);
        __half2 w0(h0,h1), w1(h2,h3), w2(l0,l1), w3(l2,l3);
        g_kfrag[obase + s] = make_uint4(*(uint32_t*)&w0, *(uint32_t*)&w1,
                                        *(uint32_t*)&w2, *(uint32_t*)&w3);
    }
    __syncthreads();

#pragma unroll
    for (int i = 0; i < 4; i++) {
        const int f = tid + i * 256;
        *(float4*)&stage[f >> 4][(f & 15) * 4] =
            *(const float4*)&vb[(size_t)(f >> 4) * QKV_LD + (f & 15) * 4];
    }
    __syncthreads();
#pragma unroll
    for (int i = 0; i < 4; i++) {
        const int s = tid + i * 256;
        const int g = s >> 5, l = s & 31;
        const int d  = (g >> 2) * 8 + (l >> 2);
        const int kk = (g & 3) * 16 + (l & 3) * 2;
        __half h0,l0,h1,l1,h2,l2,h3,l3;
        split2h(stage[kk][d],     h0, l0);
        split2h(stage[kk + 1][d], h1, l1);
        split2h(stage[kk + 8][d], h2, l2);
        split2h(stage[kk + 9][d], h3, l3);
        __half2 w0(h0,h1), w1(h2,h3), w2(l0,l1), w3(l2,l3);
        g_vfrag[obase + s] = make_uint4(*(uint32_t*)&w0, *(uint32_t*)&w1,
                                        *(uint32_t*)&w2, *(uint32_t*)&w3);
    }
}

// ---------------------------------------------------------------------------
// Tensor-core flash attention, fp16x2: Q single fp16, K/V hi+lo.
// 128 q rows/block, 8 warps; 64-key tiles; cp.async double-buffered.
// ---------------------------------------------------------------------------
__global__ void __launch_bounds__(256, 2) attn_tc_kernel(
    const unsigned int* __restrict__ mask)
{
    extern __shared__ uint4 dyn[];
    uint4*    sK    = dyn;
    uint4*    sV    = dyn + 2048;
    uint32_t* sMask = (uint32_t*)(dyn + 4096);

    const int tid  = threadIdx.x;
    const int w    = tid >> 5;
    const int lane = tid & 31;
    const int bxr  = (S_LEN / 128 - 1) - blockIdx.x;   // heavy blocks first
    const int bh   = blockIdx.y;
    const int b    = bh >> 4;
    const int h    = bh & 15;
    const int r0   = bxr * 128;

    const float* qb = g_qkv + ((size_t)b * S_LEN) * QKV_LD + h * HDIM;
    const unsigned int* mb = mask + b * S_LEN;
    const uint4* kfb = g_kfrag + ((size_t)bh * NKTILES << 10);
    const uint4* vfb = g_vfrag + ((size_t)bh * NKTILES << 10);

    const int ntiles = (r0 + 128) >> 6;

    // Q fragments: single fp16, scaled by 1/8
    uint32_t qh[4][4];
    {
        const int rlo = r0 + w * 16 + (lane >> 2);
        const float* q0 = qb + (size_t)rlo * QKV_LD;
        const float* q1 = qb + (size_t)(rlo + 8) * QKV_LD;
#pragma unroll
        for (int ks = 0; ks < 4; ks++) {
            const int c = ks * 16 + (lane & 3) * 2;
            float2 x0 = *(const float2*)&q0[c];
            float2 x1 = *(const float2*)&q1[c];
            float2 x2 = *(const float2*)&q0[c + 8];
            float2 x3 = *(const float2*)&q1[c + 8];
            qh[ks][0] = pack2h(x0.x * 0.125f, x0.y * 0.125f);
            qh[ks][1] = pack2h(x1.x * 0.125f, x1.y * 0.125f);
            qh[ks][2] = pack2h(x2.x * 0.125f, x2.y * 0.125f);
            qh[ks][3] = pack2h(x3.x * 0.125f, x3.y * 0.125f);
        }
    }

    float m_i[2] = {-1e30f, -1e30f};
    float l_i[2] = {0.f, 0.f};
    float o_acc[8][4];
#pragma unroll
    for (int dt = 0; dt < 8; dt++)
#pragma unroll
        for (int r = 0; r < 4; r++) o_acc[dt][r] = 0.f;

    const int q0g = r0 + w * 16 + (lane >> 2);

    {
#pragma unroll
        for (int i = 0; i < 4; i++) {
            const int idx = tid + i * 256;
            cp_async16(&sK[idx], kfb + idx);
            cp_async16(&sV[idx], vfb + idx);
        }
        if (tid < 16) cp_async16(&sMask[tid * 4], mb + tid * 4);
        cp_commit();
    }

    for (int t = 0; t < ntiles; t++) {
        const int buf = t & 1;
        if (t + 1 < ntiles) {
            const int nb = (t + 1) & 1;
            const uint4* srcK = kfb + ((size_t)(t + 1) << 10);
            const uint4* srcV = vfb + ((size_t)(t + 1) << 10);
#pragma unroll
            for (int i = 0; i < 4; i++) {
                const int idx = tid + i * 256;
                cp_async16(&sK[nb * 1024 + idx], srcK + idx);
                cp_async16(&sV[nb * 1024 + idx], srcV + idx);
            }
            if (tid < 16) cp_async16(&sMask[nb * 64 + tid * 4], mb + (t + 1) * 64 + tid * 4);
            cp_commit();
            cp_wait<1>();
        } else {
            cp_wait<0>();
        }
        __syncthreads();

        const int k0 = t << 6;
        const uint4* bK = sK + buf * 1024;
        const uint4* bV = sV + buf * 1024;
        const uint32_t* bM = sMask + buf * 64;

        float s[8][4];
#pragma unroll
        for (int nt = 0; nt < 8; nt++)
#pragma unroll
            for (int r = 0; r < 4; r++) s[nt][r] = 0.f;

#pragma unroll
        for (int ks = 0; ks < 4; ks++) {
#pragma unroll
            for (int nt = 0; nt < 8; nt++) {
                const uint4 v = bK[(nt * 4 + ks) * 32 + lane];
                uint32_t bfr[2] = {v.x, v.y};
                uint32_t bfl[2] = {v.z, v.w};
                mma_f16(s[nt], qh[ks], bfr);
                mma_f16(s[nt], qh[ks], bfl);
            }
        }

#pragma unroll
        for (int row = 0; row < 2; row++) {
            const int qg = q0g + row * 8;
            float mx = -1e30f;
#pragma unroll
            for (int nt = 0; nt < 8; nt++)
#pragma unroll
                for (int c = 0; c < 2; c++) {
                    const int idx = row * 2 + c;
                    const int kl  = nt * 8 + (lane & 3) * 2 + c;
                    const bool ok = (bM[kl] != 0u) && (k0 + kl <= qg);
                    s[nt][idx] = ok ? s[nt][idx] : -1e9f;
                    mx = fmaxf(mx, s[nt][idx]);
                }
            mx = fmaxf(mx, __shfl_xor_sync(0xffffffffu, mx, 1));
            mx = fmaxf(mx, __shfl_xor_sync(0xffffffffu, mx, 2));
            const float mnew = fmaxf(m_i[row], mx);
            const float corr = __expf(m_i[row] - mnew);
            float sum = 0.f;
#pragma unroll
            for (int nt = 0; nt < 8; nt++)
#pragma unroll
                for (int c = 0; c < 2; c++) {
                    const int idx = row * 2 + c;
                    const float p = __expf(s[nt][idx] - mnew);
                    s[nt][idx] = p;
                    sum += p;
                }
            sum += __shfl_xor_sync(0xffffffffu, sum, 1);
            sum += __shfl_xor_sync(0xffffffffu, sum, 2);
            l_i[row] = l_i[row] * corr + sum;
            m_i[row] = mnew;
#pragma unroll
            for (int dt = 0; dt < 8; dt++) {
                o_acc[dt][row * 2 + 0] *= corr;
                o_acc[dt][row * 2 + 1] *= corr;
            }
        }

        // PV: P single fp16, V hi+lo
#pragma unroll
        for (int ks2 = 0; ks2 < 4; ks2++) {
            uint32_t pah[4];
            pah[0] = pack2h(s[ks2*2][0],   s[ks2*2][1]);
            pah[1] = pack2h(s[ks2*2][2],   s[ks2*2][3]);
            pah[2] = pack2h(s[ks2*2+1][0], s[ks2*2+1][1]);
            pah[3] = pack2h(s[ks2*2+1][2], s[ks2*2+1][3]);
#pragma unroll
            for (int dt = 0; dt < 8; dt++) {
                const uint4 v = bV[(dt * 4 + ks2) * 32 + lane];
                uint32_t bfr[2] = {v.x, v.y};
                uint32_t bfl[2] = {v.z, v.w};
                mma_f16(o_acc[dt], pah, bfr);
                mma_f16(o_acc[dt], pah, bfl);
            }
        }
        __syncthreads();
    }

    const float inv0 = 1.f / l_i[0];
    const float inv1 = 1.f / l_i[1];
    float* ob = g_ctx + ((size_t)b * S_LEN) * DMODEL + h * HDIM;
#pragma unroll
    for (int dt = 0; dt < 8; dt++) {
        const int col = dt * 8 + (lane & 3) * 2;
        float2 o0, o1;
        o0.x = o_acc[dt][0] * inv0;  o0.y = o_acc[dt][1] * inv0;
        o1.x = o_acc[dt][2] * inv1;  o1.y = o_acc[dt][3] * inv1;
        *(float2*)&ob[(size_t)q0g * DMODEL + col]       = o0;
        *(float2*)&ob[(size_t)(q0g + 8) * DMODEL + col] = o1;
    }
}

// ---------------------------------------------------------------------------
extern "C" void kernel_launch(void* const* d_in, const int* in_sizes, int n_in,
                              void* d_out, int out_size)
{
    const float*        tokens = (const float*)d_in[0];
    const unsigned int* mask   = (const unsigned int*)d_in[1];
    const int*          seqc   = (const int*)d_in[2];
    const float*        W_qkv  = (const float*)d_in[3];
    const float*        b_qkv  = (const float*)d_in[4];
    const float*        Wq     = (const float*)d_in[5];
    const float*        bq     = (const float*)d_in[6];
    const float*        Wk     = (const float*)d_in[7];
    const float*        bk     = (const float*)d_in[8];
    const float*        Wv     = (const float*)d_in[9];
    const float*        bv     = (const float*)d_in[10];
    const float*        W_out  = (const float*)d_in[11];
    const float*        b_out  = (const float*)d_in[12];
    float*              out    = (float*)d_out;

    float* qkv = nullptr;
    float* ctx = nullptr;
    cudaGetSymbolAddress((void**)&qkv, g_qkv);
    cudaGetSymbolAddress((void**)&ctx, g_ctx);

    cudaFuncSetAttribute(attn_tc_kernel,
                         cudaFuncAttributeMaxDynamicSharedMemorySize, 66048);

    const int M = BATCH * S_LEN;   // 4096

    // 1) fused QKV projection (fp16x2 tensor cores)
    dim3 g1(QKV_LD / 128, M / 128);
    gemm_f16x2_kernel<<<g1, 256>>>(tokens, W_qkv, b_qkv, qkv, M, QKV_LD, DMODEL);

    // 2) per-position ns overwrites
    ns_kernel<<<48, 256>>>(tokens, seqc, Wq, bq, Wk, bk, Wv, bv);

    // 3) K/V presplit for attention
    dim3 gp(NKTILES, BATCH * NHEADS);
    presplit_kernel<<<gp, 256>>>();

    // 4) attention
    dim3 g2(S_LEN / 128, BATCH * NHEADS);
    attn_tc_kernel<<<g2, 256, 66048>>>(mask);

    // 5) output projection (fp16x2 tensor cores)
    dim3 g3(DMODEL / 128, M / 128);
    gemm_f16x2_kernel<<<g3, 256>>>(ctx, W_out, b_out, out, M, DMODEL, DMODEL);
}

// round 9
// speedup vs baseline: 1.6274x; 1.1296x over previous
#include <cuda_runtime.h>
#include <cuda_fp16.h>
#include <cstdint>

#define S_LEN   2048
#define DMODEL  1024
#define BATCH   2
#define NHEADS  16
#define HDIM    64
#define QKV_LD  3072
#define NKTILES (S_LEN / 64)
#define MROWS   (BATCH * S_LEN)   // 4096
#define MBLK    (MROWS / 128)     // 32
#define KIT     (DMODEL / 32)     // 32

__device__ float g_qkv[(size_t)BATCH * S_LEN * QKV_LD];
// attention K / V^T fragments, fp16 hi/lo
__device__ uint4 g_kfrag[(size_t)BATCH * NHEADS * NKTILES * 1024];
__device__ uint4 g_vfrag[(size_t)BATCH * NHEADS * NKTILES * 1024];
// GEMM fragment operands
__device__ uint4 g_wqkv_frag[(size_t)(QKV_LD / 128) * KIT * 1024];  // B hi/lo
__device__ uint4 g_wout_frag[(size_t)(DMODEL / 128) * KIT * 1024];  // B hi/lo
__device__ uint4 g_atok_frag[(size_t)MBLK * KIT * 512];             // A fp16
__device__ uint4 g_actx_frag[(size_t)MBLK * KIT * 512];             // A fp16 (from attn)

// ---------------------------------------------------------------------------
__device__ __forceinline__ void mma_f16(float* d, const uint32_t* a, const uint32_t* b) {
    asm volatile(
        "mma.sync.aligned.m16n8k16.row.col.f32.f16.f16.f32 "
        "{%0,%1,%2,%3}, {%4,%5,%6,%7}, {%8,%9}, {%0,%1,%2,%3};\n"
        : "+f"(d[0]), "+f"(d[1]), "+f"(d[2]), "+f"(d[3])
        : "r"(a[0]), "r"(a[1]), "r"(a[2]), "r"(a[3]), "r"(b[0]), "r"(b[1]));
}

__device__ __forceinline__ void split2h(float x, __half& hi, __half& lo) {
    hi = __float2half_rn(x);
    lo = __float2half_rn(x - __half2float(hi));
}

__device__ __forceinline__ uint32_t pack2h(float x, float y) {
    __half2 h = __floats2half2_rn(x, y);
    return *(uint32_t*)&h;
}

__device__ __forceinline__ void cp_async16(void* smem_ptr, const void* gptr) {
    uint32_t sa = (uint32_t)__cvta_generic_to_shared(smem_ptr);
    asm volatile("cp.async.cg.shared.global [%0], [%1], 16;\n" :: "r"(sa), "l"(gptr));
}
__device__ __forceinline__ void cp_commit() {
    asm volatile("cp.async.commit_group;\n");
}
template <int N>
__device__ __forceinline__ void cp_wait() {
    asm volatile("cp.async.wait_group %0;\n" :: "n"(N));
}

// ---------------------------------------------------------------------------
// Presplit W [1024, N] -> B-fragment chunks (nb, it): 1024 uint4.
// slot = (ks*16 + n8)*32 + lane; n = nb*128+n8*8+(lane>>2), k = it*32+ks*16+(lane&3)*2
// uint4 = {hi(Wk,Wk+1), hi(Wk+8,Wk+9), lo(Wk,Wk+1), lo(Wk+8,Wk+9)}
// ---------------------------------------------------------------------------
__global__ void __launch_bounds__(256) presplit_w_kernel(
    const float* __restrict__ W, uint4* __restrict__ out, int N)
{
    const int it = blockIdx.x;
    const int nb = blockIdx.y;
    uint4* chunk = out + ((size_t)nb * KIT + it) * 1024;
#pragma unroll
    for (int i = 0; i < 4; i++) {
        const int s    = threadIdx.x + i * 256;
        const int lane = s & 31;
        const int n8   = (s >> 5) & 15;
        const int ks   = s >> 9;
        const int n = nb * 128 + n8 * 8 + (lane >> 2);
        const int k = it * 32 + ks * 16 + (lane & 3) * 2;
        const float b0 = W[(size_t)k * N + n];
        const float b1 = W[(size_t)(k + 1) * N + n];
        const float b2 = W[(size_t)(k + 8) * N + n];
        const float b3 = W[(size_t)(k + 9) * N + n];
        __half h0, l0, h1, l1, h2, l2, h3, l3;
        split2h(b0, h0, l0); split2h(b1, h1, l1);
        split2h(b2, h2, l2); split2h(b3, h3, l3);
        __half2 whi0(h0, h1), whi1(h2, h3), wlo0(l0, l1), wlo1(l2, l3);
        chunk[s] = make_uint4(*(uint32_t*)&whi0, *(uint32_t*)&whi1,
                              *(uint32_t*)&wlo0, *(uint32_t*)&wlo1);
    }
}

// ---------------------------------------------------------------------------
// Presplit A [4096, 1024] -> single-fp16 A-fragment chunks (mb, it): 512 uint4.
// slot = (ks*8 + mt)*32 + lane; m = mb*128+mt*16+(lane>>2), k = it*32+ks*16+(lane&3)*2
// uint4 = {A(m,k:k+1), A(m+8,k:k+1), A(m,k+8:k+9), A(m+8,k+8:k+9)}
// ---------------------------------------------------------------------------
__global__ void __launch_bounds__(256) presplit_a_kernel(
    const float* __restrict__ A, uint4* __restrict__ out)
{
    const int it = blockIdx.x;
    const int mb = blockIdx.y;
    uint4* chunk = out + ((size_t)mb * KIT + it) * 512;
#pragma unroll
    for (int i = 0; i < 2; i++) {
        const int s    = threadIdx.x + i * 256;
        const int lane = s & 31;
        const int mt   = (s >> 5) & 7;
        const int ks   = s >> 8;
        const int m = mb * 128 + mt * 16 + (lane >> 2);
        const int k = it * 32 + ks * 16 + (lane & 3) * 2;
        const float2 r0 = *(const float2*)&A[(size_t)m * DMODEL + k];
        const float2 r1 = *(const float2*)&A[(size_t)(m + 8) * DMODEL + k];
        const float2 r2 = *(const float2*)&A[(size_t)m * DMODEL + k + 8];
        const float2 r3 = *(const float2*)&A[(size_t)(m + 8) * DMODEL + k + 8];
        chunk[s] = make_uint4(pack2h(r0.x, r0.y), pack2h(r1.x, r1.y),
                              pack2h(r2.x, r2.y), pack2h(r3.x, r3.y));
    }
}

// ---------------------------------------------------------------------------
// Fragment GEMM (fp16x2): C[4096, N] = A @ W + bias.
// BM=BN=128, BK=32; 8 warps, warp tile 64x32; cp.async double-buffered.
// Per warp-iter: 8 LDS.128 x2(ks), 64 MMAs.
// ---------------------------------------------------------------------------
__global__ void __launch_bounds__(256) gemm_frag_kernel(
    const uint4* __restrict__ Afrag, const uint4* __restrict__ Bfrag,
    const float* __restrict__ bias, float* __restrict__ C, int N)
{
    extern __shared__ uint4 dyn[];
    uint4* sA = dyn;            // [2][512]
    uint4* sB = dyn + 1024;     // [2][1024]

    const int tid    = threadIdx.x;
    const int lane   = tid & 31;
    const int wid    = tid >> 5;
    const int nb     = blockIdx.x;
    const int mb     = blockIdx.y;
    const int warp_m = (wid >> 2);   // 0/1
    const int warp_n = (wid & 3);    // 0..3

    const uint4* Ab = Afrag + (size_t)mb * KIT * 512;
    const uint4* Bb = Bfrag + (size_t)nb * KIT * 1024;

    float acc[4][4][4];
#pragma unroll
    for (int mi = 0; mi < 4; mi++)
#pragma unroll
        for (int ni = 0; ni < 4; ni++)
#pragma unroll
            for (int r = 0; r < 4; r++) acc[mi][ni][r] = 0.f;

    // prologue
#pragma unroll
    for (int i = 0; i < 2; i++) cp_async16(&sA[tid + i * 256], Ab + tid + i * 256);
#pragma unroll
    for (int i = 0; i < 4; i++) cp_async16(&sB[tid + i * 256], Bb + tid + i * 256);
    cp_commit();

    for (int it = 0; it < KIT; it++) {
        const int buf = it & 1;
        if (it + 1 < KIT) {
            const int nbuf = (it + 1) & 1;
            const uint4* na = Ab + (size_t)(it + 1) * 512;
            const uint4* nb4 = Bb + (size_t)(it + 1) * 1024;
#pragma unroll
            for (int i = 0; i < 2; i++)
                cp_async16(&sA[nbuf * 512 + tid + i * 256], na + tid + i * 256);
#pragma unroll
            for (int i = 0; i < 4; i++)
                cp_async16(&sB[nbuf * 1024 + tid + i * 256], nb4 + tid + i * 256);
            cp_commit();
            cp_wait<1>();
        } else {
            cp_wait<0>();
        }
        __syncthreads();

        const uint4* bA = sA + buf * 512;
        const uint4* bB = sB + buf * 1024;

#pragma unroll
        for (int ks = 0; ks < 2; ks++) {
            uint4 ah[4], bb[4];
#pragma unroll
            for (int mi = 0; mi < 4; mi++)
                ah[mi] = bA[(ks * 8 + warp_m * 4 + mi) * 32 + lane];
#pragma unroll
            for (int ni = 0; ni < 4; ni++)
                bb[ni] = bB[(ks * 16 + warp_n * 4 + ni) * 32 + lane];
#pragma unroll
            for (int mi = 0; mi < 4; mi++) {
                const uint32_t* ap = (const uint32_t*)&ah[mi];
#pragma unroll
                for (int ni = 0; ni < 4; ni++) {
                    uint32_t bfr[2] = {bb[ni].x, bb[ni].y};
                    uint32_t bfl[2] = {bb[ni].z, bb[ni].w};
                    mma_f16(acc[mi][ni], ap, bfr);
                    mma_f16(acc[mi][ni], ap, bfl);
                }
            }
        }
        __syncthreads();
    }

    // epilogue
    const int bm = mb * 128;
    const int bn = nb * 128;
#pragma unroll
    for (int mi = 0; mi < 4; mi++) {
        const int row = bm + warp_m * 64 + mi * 16 + (lane >> 2);
#pragma unroll
        for (int ni = 0; ni < 4; ni++) {
            const int col = bn + warp_n * 32 + ni * 8 + (lane & 3) * 2;
            const float2 bv = *(const float2*)&bias[col];
            float2 o0, o1;
            o0.x = acc[mi][ni][0] + bv.x;  o0.y = acc[mi][ni][1] + bv.y;
            o1.x = acc[mi][ni][2] + bv.x;  o1.y = acc[mi][ni][3] + bv.y;
            *(float2*)&C[(size_t)row * N + col]       = o0;
            *(float2*)&C[(size_t)(row + 8) * N + col] = o1;
        }
    }
}

// ---------------------------------------------------------------------------
// ns overwrite (proven R5 version)
// ---------------------------------------------------------------------------
__global__ void __launch_bounds__(256) ns_kernel(
    const float* __restrict__ tokens, const int* __restrict__ seqc,
    const float* __restrict__ Wq, const float* __restrict__ bq,
    const float* __restrict__ Wk, const float* __restrict__ bk,
    const float* __restrict__ Wv, const float* __restrict__ bv)
{
    __shared__ float st[DMODEL];
    const int bxid = blockIdx.x;
    const int mat = bxid >> 4;
    const int b   = (bxid >> 3) & 1;
    const int n   = bxid & 7;

    const int pos = *seqc;
    const int row = pos + n;
    if (pos < 0 || row < 0 || row >= S_LEN) return;

    const float* W; const float* bb;
    if (mat == 0)      { W = Wq; bb = bq; }
    else if (mat == 1) { W = Wk; bb = bk; }
    else               { W = Wv; bb = bv; }
    W  += (size_t)n * DMODEL * DMODEL;
    bb += n * DMODEL;

    const float* trow = tokens + ((size_t)b * S_LEN + row) * DMODEL;
    const int tid = threadIdx.x;
    *(float4*)&st[tid * 4] = *(const float4*)&trow[tid * 4];
    __syncthreads();

    float acc[4];
#pragma unroll
    for (int j = 0; j < 4; j++) acc[j] = bb[tid + 256 * j];

    for (int d = 0; d < DMODEL; d++) {
        const float td = st[d];
        const float* wr = W + (size_t)d * DMODEL;
#pragma unroll
        for (int j = 0; j < 4; j++) acc[j] += td * wr[tid + 256 * j];
    }

    float* out = g_qkv + ((size_t)b * S_LEN + row) * QKV_LD + mat * DMODEL;
#pragma unroll
    for (int j = 0; j < 4; j++) out[tid + 256 * j] = acc[j];
}

// ---------------------------------------------------------------------------
// Presplit K and V^T -> fragment-major fp16 hi/lo (unchanged from R8)
// ---------------------------------------------------------------------------
__global__ void __launch_bounds__(256) presplit_kernel()
{
    __shared__ float stage[64][68];
    const int tile = blockIdx.x;
    const int bh   = blockIdx.y;
    const int b    = bh >> 4;
    const int h    = bh & 15;
    const int tid  = threadIdx.x;

    const float* kb = g_qkv + ((size_t)b * S_LEN + tile * 64) * QKV_LD + DMODEL + h * HDIM;
    const float* vb = kb + DMODEL;
    const size_t obase = ((size_t)bh * NKTILES + tile) << 10;

#pragma unroll
    for (int i = 0; i < 4; i++) {
        const int f = tid + i * 256;
        *(float4*)&stage[f >> 4][(f & 15) * 4] =
            *(const float4*)&kb[(size_t)(f >> 4) * QKV_LD + (f & 15) * 4];
    }
    __syncthreads();
#pragma unroll
    for (int i = 0; i < 4; i++) {
        const int s = tid + i * 256;
        const int g = s >> 5, l = s & 31;
        const int key = (g >> 2) * 8 + (l >> 2);
        const int c   = (g & 3) * 16 + (l & 3) * 2;
        __half h0,l0,h1,l1,h2,l2,h3,l3;
        split2h(stage[key][c],     h0, l0);
        split2h(stage[key][c + 1], h1, l1);
        split2h(stage[key][c + 8], h2, l2);
        split2h(stage[key][c + 9], h3, l3);
        __half2 w0(h0,h1), w1(h2,h3), w2(l0,l1), w3(l2,l3);
        g_kfrag[obase + s] = make_uint4(*(uint32_t*)&w0, *(uint32_t*)&w1,
                                        *(uint32_t*)&w2, *(uint32_t*)&w3);
    }
    __syncthreads();

#pragma unroll
    for (int i = 0; i < 4; i++) {
        const int f = tid + i * 256;
        *(float4*)&stage[f >> 4][(f & 15) * 4] =
            *(const float4*)&vb[(size_t)(f >> 4) * QKV_LD + (f & 15) * 4];
    }
    __syncthreads();
#pragma unroll
    for (int i = 0; i < 4; i++) {
        const int s = tid + i * 256;
        const int g = s >> 5, l = s & 31;
        const int d  = (g >> 2) * 8 + (l >> 2);
        const int kk = (g & 3) * 16 + (l & 3) * 2;
        __half h0,l0,h1,l1,h2,l2,h3,l3;
        split2h(stage[kk][d],     h0, l0);
        split2h(stage[kk + 1][d], h1, l1);
        split2h(stage[kk + 8][d], h2, l2);
        split2h(stage[kk + 9][d], h3, l3);
        __half2 w0(h0,h1), w1(h2,h3), w2(l0,l1), w3(l2,l3);
        g_vfrag[obase + s] = make_uint4(*(uint32_t*)&w0, *(uint32_t*)&w1,
                                        *(uint32_t*)&w2, *(uint32_t*)&w3);
    }
}

// ---------------------------------------------------------------------------
// Tensor-core flash attention, fp16x2. Epilogue emits ctx A-fragments
// directly (fp16) for the out-projection frag-GEMM.
// ---------------------------------------------------------------------------
__global__ void __launch_bounds__(256, 2) attn_tc_kernel(
    const unsigned int* __restrict__ mask)
{
    extern __shared__ uint4 dyn[];
    uint4*    sK    = dyn;
    uint4*    sV    = dyn + 2048;
    uint32_t* sMask = (uint32_t*)(dyn + 4096);

    const int tid  = threadIdx.x;
    const int w    = tid >> 5;
    const int lane = tid & 31;
    const int bxr  = (S_LEN / 128 - 1) - blockIdx.x;   // heavy blocks first
    const int bh   = blockIdx.y;
    const int b    = bh >> 4;
    const int h    = bh & 15;
    const int r0   = bxr * 128;

    const float* qb = g_qkv + ((size_t)b * S_LEN) * QKV_LD + h * HDIM;
    const unsigned int* mb = mask + b * S_LEN;
    const uint4* kfb = g_kfrag + ((size_t)bh * NKTILES << 10);
    const uint4* vfb = g_vfrag + ((size_t)bh * NKTILES << 10);

    const int ntiles = (r0 + 128) >> 6;

    uint32_t qh[4][4];
    {
        const int rlo = r0 + w * 16 + (lane >> 2);
        const float* q0 = qb + (size_t)rlo * QKV_LD;
        const float* q1 = qb + (size_t)(rlo + 8) * QKV_LD;
#pragma unroll
        for (int ks = 0; ks < 4; ks++) {
            const int c = ks * 16 + (lane & 3) * 2;
            float2 x0 = *(const float2*)&q0[c];
            float2 x1 = *(const float2*)&q1[c];
            float2 x2 = *(const float2*)&q0[c + 8];
            float2 x3 = *(const float2*)&q1[c + 8];
            qh[ks][0] = pack2h(x0.x * 0.125f, x0.y * 0.125f);
            qh[ks][1] = pack2h(x1.x * 0.125f, x1.y * 0.125f);
            qh[ks][2] = pack2h(x2.x * 0.125f, x2.y * 0.125f);
            qh[ks][3] = pack2h(x3.x * 0.125f, x3.y * 0.125f);
        }
    }

    float m_i[2] = {-1e30f, -1e30f};
    float l_i[2] = {0.f, 0.f};
    float o_acc[8][4];
#pragma unroll
    for (int dt = 0; dt < 8; dt++)
#pragma unroll
        for (int r = 0; r < 4; r++) o_acc[dt][r] = 0.f;

    const int q0g = r0 + w * 16 + (lane >> 2);

    {
#pragma unroll
        for (int i = 0; i < 4; i++) {
            const int idx = tid + i * 256;
            cp_async16(&sK[idx], kfb + idx);
            cp_async16(&sV[idx], vfb + idx);
        }
        if (tid < 16) cp_async16(&sMask[tid * 4], mb + tid * 4);
        cp_commit();
    }

    for (int t = 0; t < ntiles; t++) {
        const int buf = t & 1;
        if (t + 1 < ntiles) {
            const int nb = (t + 1) & 1;
            const uint4* srcK = kfb + ((size_t)(t + 1) << 10);
            const uint4* srcV = vfb + ((size_t)(t + 1) << 10);
#pragma unroll
            for (int i = 0; i < 4; i++) {
                const int idx = tid + i * 256;
                cp_async16(&sK[nb * 1024 + idx], srcK + idx);
                cp_async16(&sV[nb * 1024 + idx], srcV + idx);
            }
            if (tid < 16) cp_async16(&sMask[nb * 64 + tid * 4], mb + (t + 1) * 64 + tid * 4);
            cp_commit();
            cp_wait<1>();
        } else {
            cp_wait<0>();
        }
        __syncthreads();

        const int k0 = t << 6;
        const uint4* bK = sK + buf * 1024;
        const uint4* bV = sV + buf * 1024;
        const uint32_t* bM = sMask + buf * 64;

        float s[8][4];
#pragma unroll
        for (int nt = 0; nt < 8; nt++)
#pragma unroll
            for (int r = 0; r < 4; r++) s[nt][r] = 0.f;

#pragma unroll
        for (int ks = 0; ks < 4; ks++) {
#pragma unroll
            for (int nt = 0; nt < 8; nt++) {
                const uint4 v = bK[(nt * 4 + ks) * 32 + lane];
                uint32_t bfr[2] = {v.x, v.y};
                uint32_t bfl[2] = {v.z, v.w};
                mma_f16(s[nt], qh[ks], bfr);
                mma_f16(s[nt], qh[ks], bfl);
            }
        }

#pragma unroll
        for (int row = 0; row < 2; row++) {
            const int qg = q0g + row * 8;
            float mx = -1e30f;
#pragma unroll
            for (int nt = 0; nt < 8; nt++)
#pragma unroll
                for (int c = 0; c < 2; c++) {
                    const int idx = row * 2 + c;
                    const int kl  = nt * 8 + (lane & 3) * 2 + c;
                    const bool ok = (bM[kl] != 0u) && (k0 + kl <= qg);
                    s[nt][idx] = ok ? s[nt][idx] : -1e9f;
                    mx = fmaxf(mx, s[nt][idx]);
                }
            mx = fmaxf(mx, __shfl_xor_sync(0xffffffffu, mx, 1));
            mx = fmaxf(mx, __shfl_xor_sync(0xffffffffu, mx, 2));
            const float mnew = fmaxf(m_i[row], mx);
            const float corr = __expf(m_i[row] - mnew);
            float sum = 0.f;
#pragma unroll
            for (int nt = 0; nt < 8; nt++)
#pragma unroll
                for (int c = 0; c < 2; c++) {
                    const int idx = row * 2 + c;
                    const float p = __expf(s[nt][idx] - mnew);
                    s[nt][idx] = p;
                    sum += p;
                }
            sum += __shfl_xor_sync(0xffffffffu, sum, 1);
            sum += __shfl_xor_sync(0xffffffffu, sum, 2);
            l_i[row] = l_i[row] * corr + sum;
            m_i[row] = mnew;
#pragma unroll
            for (int dt = 0; dt < 8; dt++) {
                o_acc[dt][row * 2 + 0] *= corr;
                o_acc[dt][row * 2 + 1] *= corr;
            }
        }

#pragma unroll
        for (int ks2 = 0; ks2 < 4; ks2++) {
            uint32_t pah[4];
            pah[0] = pack2h(s[ks2*2][0],   s[ks2*2][1]);
            pah[1] = pack2h(s[ks2*2][2],   s[ks2*2][3]);
            pah[2] = pack2h(s[ks2*2+1][0], s[ks2*2+1][1]);
            pah[3] = pack2h(s[ks2*2+1][2], s[ks2*2+1][3]);
#pragma unroll
            for (int dt = 0; dt < 8; dt++) {
                const uint4 v = bV[(dt * 4 + ks2) * 32 + lane];
                uint32_t bfr[2] = {v.x, v.y};
                uint32_t bfl[2] = {v.z, v.w};
                mma_f16(o_acc[dt], pah, bfr);
                mma_f16(o_acc[dt], pah, bfl);
            }
        }
        __syncthreads();
    }

    // ---- epilogue: emit ctx A-fragments (fp16) directly ----
    const float inv0 = 1.f / l_i[0];
    const float inv1 = 1.f / l_i[1];
    uint4* dst = g_actx_frag + ((size_t)(b * 16 + (r0 >> 7)) * KIT) * 512;
#pragma unroll
    for (int f = 0; f < 4; f++) {
        const int it  = h * 2 + (f >> 1);
        const int ks  = f & 1;
        const int dt0 = f * 2, dt1 = f * 2 + 1;
        uint4 u;
        u.x = pack2h(o_acc[dt0][0] * inv0, o_acc[dt0][1] * inv0);
        u.y = pack2h(o_acc[dt0][2] * inv1, o_acc[dt0][3] * inv1);
        u.z = pack2h(o_acc[dt1][0] * inv0, o_acc[dt1][1] * inv0);
        u.w = pack2h(o_acc[dt1][2] * inv1, o_acc[dt1][3] * inv1);
        dst[(size_t)it * 512 + (ks * 8 + w) * 32 + lane] = u;
    }
}

// ---------------------------------------------------------------------------
extern "C" void kernel_launch(void* const* d_in, const int* in_sizes, int n_in,
                              void* d_out, int out_size)
{
    const float*        tokens = (const float*)d_in[0];
    const unsigned int* mask   = (const unsigned int*)d_in[1];
    const int*          seqc   = (const int*)d_in[2];
    const float*        W_qkv  = (const float*)d_in[3];
    const float*        b_qkv  = (const float*)d_in[4];
    const float*        Wq     = (const float*)d_in[5];
    const float*        bq     = (const float*)d_in[6];
    const float*        Wk     = (const float*)d_in[7];
    const float*        bk     = (const float*)d_in[8];
    const float*        Wv     = (const float*)d_in[9];
    const float*        bv     = (const float*)d_in[10];
    const float*        W_out  = (const float*)d_in[11];
    const float*        b_out  = (const float*)d_in[12];
    float*              out    = (float*)d_out;

    float* qkv = nullptr;
    uint4 *wqkvF = nullptr, *woutF = nullptr, *atokF = nullptr, *actxF = nullptr;
    cudaGetSymbolAddress((void**)&qkv, g_qkv);
    cudaGetSymbolAddress((void**)&wqkvF, g_wqkv_frag);
    cudaGetSymbolAddress((void**)&woutF, g_wout_frag);
    cudaGetSymbolAddress((void**)&atokF, g_atok_frag);
    cudaGetSymbolAddress((void**)&actxF, g_actx_frag);

    cudaFuncSetAttribute(attn_tc_kernel,
                         cudaFuncAttributeMaxDynamicSharedMemorySize, 66048);
    cudaFuncSetAttribute(gemm_frag_kernel,
                         cudaFuncAttributeMaxDynamicSharedMemorySize, 49152);

    // one-shot operand presplits
    dim3 gw1(KIT, QKV_LD / 128);
    presplit_w_kernel<<<gw1, 256>>>(W_qkv, wqkvF, QKV_LD);
    dim3 gw2(KIT, DMODEL / 128);
    presplit_w_kernel<<<gw2, 256>>>(W_out, woutF, DMODEL);
    dim3 ga(KIT, MBLK);
    presplit_a_kernel<<<ga, 256>>>(tokens, atokF);

    // 1) QKV projection (frag tensor-core GEMM)
    dim3 g1(QKV_LD / 128, MBLK);
    gemm_frag_kernel<<<g1, 256, 49152>>>(atokF, wqkvF, b_qkv, qkv, QKV_LD);

    // 2) per-position ns overwrites
    ns_kernel<<<48, 256>>>(tokens, seqc, Wq, bq, Wk, bk, Wv, bv);

    // 3) K/V presplit for attention
    dim3 gp(NKTILES, BATCH * NHEADS);
    presplit_kernel<<<gp, 256>>>();

    // 4) attention (emits ctx A-fragments)
    dim3 g2(S_LEN / 128, BATCH * NHEADS);
    attn_tc_kernel<<<g2, 256, 66048>>>(mask);

    // 5) output projection (frag tensor-core GEMM) -> d_out
    dim3 g3(DMODEL / 128, MBLK);
    gemm_frag_kernel<<<g3, 256, 49152>>>(actxF, woutF, b_out, out, DMODEL);
}

// round 10
// speedup vs baseline: 2.6155x; 1.6071x over previous
#include <cuda_runtime.h>
#include <cuda_fp16.h>
#include <cstdint>

#define S_LEN   2048
#define DMODEL  1024
#define BATCH   2
#define NHEADS  16
#define HDIM    64
#define QKV_LD  3072
#define NKTILES (S_LEN / 64)
#define MROWS   (BATCH * S_LEN)   // 4096
#define MBLK    (MROWS / 128)     // 32
#define KIT     (DMODEL / 32)     // 32

__device__ float g_q[(size_t)MROWS * DMODEL];           // dense Q fp32
__device__ uint4 g_kfrag[(size_t)BATCH * NHEADS * NKTILES * 1024];
__device__ uint4 g_vfrag[(size_t)BATCH * NHEADS * NKTILES * 1024];
__device__ uint4 g_wqkv_frag[(size_t)(QKV_LD / 128) * KIT * 1024];
__device__ uint4 g_wout_frag[(size_t)(DMODEL / 128) * KIT * 1024];
__device__ uint4 g_atok_frag[(size_t)MBLK * KIT * 512];
__device__ uint4 g_actx_frag[(size_t)MBLK * KIT * 512];

// ---------------------------------------------------------------------------
__device__ __forceinline__ void mma_f16(float* d, const uint32_t* a, const uint32_t* b) {
    asm volatile(
        "mma.sync.aligned.m16n8k16.row.col.f32.f16.f16.f32 "
        "{%0,%1,%2,%3}, {%4,%5,%6,%7}, {%8,%9}, {%0,%1,%2,%3};\n"
        : "+f"(d[0]), "+f"(d[1]), "+f"(d[2]), "+f"(d[3])
        : "r"(a[0]), "r"(a[1]), "r"(a[2]), "r"(a[3]), "r"(b[0]), "r"(b[1]));
}

__device__ __forceinline__ void split2h(float x, __half& hi, __half& lo) {
    hi = __float2half_rn(x);
    lo = __float2half_rn(x - __half2float(hi));
}

__device__ __forceinline__ uint32_t pack2h(float x, float y) {
    __half2 h = __floats2half2_rn(x, y);
    return *(uint32_t*)&h;
}

__device__ __forceinline__ void cp_async16(void* smem_ptr, const void* gptr) {
    uint32_t sa = (uint32_t)__cvta_generic_to_shared(smem_ptr);
    asm volatile("cp.async.cg.shared.global [%0], [%1], 16;\n" :: "r"(sa), "l"(gptr));
}
__device__ __forceinline__ void cp_commit() {
    asm volatile("cp.async.commit_group;\n");
}
template <int N>
__device__ __forceinline__ void cp_wait() {
    asm volatile("cp.async.wait_group %0;\n" :: "n"(N));
}

__device__ __forceinline__ bool in_ns(int s, int pos) {
    return (unsigned)(s - pos) < 8u;
}

// ---------------------------------------------------------------------------
// Combined presplit: [0,768) W_qkv B-frags, [768,1024) W_out B-frags,
// [1024,2048) tokens A-frags.
// ---------------------------------------------------------------------------
__global__ void __launch_bounds__(256) presplit_all_kernel(
    const float* __restrict__ tokens, const float* __restrict__ W_qkv,
    const float* __restrict__ W_out)
{
    const int bid = blockIdx.x;
    if (bid < 1024) {
        // W presplit
        const float* W;
        uint4* out;
        int N, j;
        if (bid < 768) { W = W_qkv; out = g_wqkv_frag; N = QKV_LD; j = bid; }
        else           { W = W_out; out = g_wout_frag; N = DMODEL; j = bid - 768; }
        const int it = j & 31;
        const int nb = j >> 5;
        uint4* chunk = out + ((size_t)nb * KIT + it) * 1024;
#pragma unroll
        for (int i = 0; i < 4; i++) {
            const int s    = threadIdx.x + i * 256;
            const int lane = s & 31;
            const int n8   = (s >> 5) & 15;
            const int ks   = s >> 9;
            const int n = nb * 128 + n8 * 8 + (lane >> 2);
            const int k = it * 32 + ks * 16 + (lane & 3) * 2;
            const float b0 = W[(size_t)k * N + n];
            const float b1 = W[(size_t)(k + 1) * N + n];
            const float b2 = W[(size_t)(k + 8) * N + n];
            const float b3 = W[(size_t)(k + 9) * N + n];
            __half h0, l0, h1, l1, h2, l2, h3, l3;
            split2h(b0, h0, l0); split2h(b1, h1, l1);
            split2h(b2, h2, l2); split2h(b3, h3, l3);
            __half2 whi0(h0, h1), whi1(h2, h3), wlo0(l0, l1), wlo1(l2, l3);
            chunk[s] = make_uint4(*(uint32_t*)&whi0, *(uint32_t*)&whi1,
                                  *(uint32_t*)&wlo0, *(uint32_t*)&wlo1);
        }
    } else {
        // tokens A presplit
        const int j  = bid - 1024;
        const int it = j & 31;
        const int mb = j >> 5;
        uint4* chunk = g_atok_frag + ((size_t)mb * KIT + it) * 512;
#pragma unroll
        for (int i = 0; i < 2; i++) {
            const int s    = threadIdx.x + i * 256;
            const int lane = s & 31;
            const int mt   = (s >> 5) & 7;
            const int ks   = s >> 8;
            const int m = mb * 128 + mt * 16 + (lane >> 2);
            const int k = it * 32 + ks * 16 + (lane & 3) * 2;
            const float2 r0 = *(const float2*)&tokens[(size_t)m * DMODEL + k];
            const float2 r1 = *(const float2*)&tokens[(size_t)(m + 8) * DMODEL + k];
            const float2 r2 = *(const float2*)&tokens[(size_t)m * DMODEL + k + 8];
            const float2 r3 = *(const float2*)&tokens[(size_t)(m + 8) * DMODEL + k + 8];
            chunk[s] = make_uint4(pack2h(r0.x, r0.y), pack2h(r1.x, r1.y),
                                  pack2h(r2.x, r2.y), pack2h(r3.x, r3.y));
        }
    }
}

// ---------------------------------------------------------------------------
// QKV frag GEMM + fused frag emission + fused ns blocks.
// Grid: 816 blocks 1D. [0,768): GEMM tiles (nb = bid%24, mb = bid/24).
// [768,816): ns matvec blocks.
// ---------------------------------------------------------------------------
__global__ void __launch_bounds__(256) gemm_qkv_kernel(
    const float* __restrict__ bias, const float* __restrict__ tokens,
    const int* __restrict__ seqc,
    const float* __restrict__ Wq, const float* __restrict__ bq,
    const float* __restrict__ Wk, const float* __restrict__ bk,
    const float* __restrict__ Wv, const float* __restrict__ bv)
{
    extern __shared__ uint4 dyn[];

    if (blockIdx.x >= 768) {
        // ---------------- ns block ----------------
        float* st = (float*)dyn;          // 4KB token row
        const int bid2 = blockIdx.x - 768;
        const int mat = bid2 >> 4;
        const int b   = (bid2 >> 3) & 1;
        const int n   = bid2 & 7;
        const int pos = *seqc;
        const int row = pos + n;
        if (pos < 0 || row < 0 || row >= S_LEN) return;

        const float* W; const float* bb;
        if (mat == 0)      { W = Wq; bb = bq; }
        else if (mat == 1) { W = Wk; bb = bk; }
        else               { W = Wv; bb = bv; }
        W  += (size_t)n * DMODEL * DMODEL;
        bb += n * DMODEL;

        const float* trow = tokens + ((size_t)b * S_LEN + row) * DMODEL;
        const int tid = threadIdx.x;
        *(float4*)&st[tid * 4] = *(const float4*)&trow[tid * 4];
        __syncthreads();

        float acc[4];
#pragma unroll
        for (int j = 0; j < 4; j++) acc[j] = bb[tid + 256 * j];
        for (int d = 0; d < DMODEL; d++) {
            const float td = st[d];
            const float* wr = W + (size_t)d * DMODEL;
#pragma unroll
            for (int j = 0; j < 4; j++) acc[j] += td * wr[tid + 256 * j];
        }

        if (mat == 0) {
#pragma unroll
            for (int j = 0; j < 4; j++)
                g_q[((size_t)b * S_LEN + row) * DMODEL + tid + 256 * j] = acc[j];
        } else {
            uint4* frag = (mat == 1) ? g_kfrag : g_vfrag;
            const int loc = row & 63;
            const int tile = row >> 6;
#pragma unroll
            for (int j = 0; j < 4; j++) {
                const int col = tid + 256 * j;
                const int h = col >> 6;
                const int c = col & 63;
                const int bh = b * 16 + h;
                __half hi, lo;
                split2h(acc[j], hi, lo);
                int slot, word, half;
                if (mat == 1) {   // K element (loc, c)
                    slot = ((loc >> 3) * 4 + (c >> 4)) * 32 + (loc & 7) * 4 + ((c & 7) >> 1);
                    word = (c >> 3) & 1;
                    half = c & 1;
                } else {          // V element (d=c, kk=loc)
                    slot = ((c >> 3) * 4 + (loc >> 4)) * 32 + (c & 7) * 4 + ((loc & 7) >> 1);
                    word = (loc >> 3) & 1;
                    half = loc & 1;
                }
                __half* p = (__half*)(frag + ((size_t)bh * NKTILES + tile) * 1024 + slot);
                p[word * 2 + half]       = hi;
                p[(word + 2) * 2 + half] = lo;
            }
        }
        return;
    }

    // ---------------- GEMM tile ----------------
    uint4* sA = dyn;            // [2][512]
    uint4* sB = dyn + 1024;     // [2][1024]

    const int tid    = threadIdx.x;
    const int lane   = tid & 31;
    const int wid    = tid >> 5;
    const int nb     = blockIdx.x % 24;
    const int mb     = blockIdx.x / 24;
    const int warp_m = (wid >> 2);
    const int warp_n = (wid & 3);

    const uint4* Ab = g_atok_frag + (size_t)mb * KIT * 512;
    const uint4* Bb = g_wqkv_frag + (size_t)nb * KIT * 1024;

    float acc[4][4][4];
#pragma unroll
    for (int mi = 0; mi < 4; mi++)
#pragma unroll
        for (int ni = 0; ni < 4; ni++)
#pragma unroll
            for (int r = 0; r < 4; r++) acc[mi][ni][r] = 0.f;

#pragma unroll
    for (int i = 0; i < 2; i++) cp_async16(&sA[tid + i * 256], Ab + tid + i * 256);
#pragma unroll
    for (int i = 0; i < 4; i++) cp_async16(&sB[tid + i * 256], Bb + tid + i * 256);
    cp_commit();

    for (int it = 0; it < KIT; it++) {
        const int buf = it & 1;
        if (it + 1 < KIT) {
            const int nbuf = (it + 1) & 1;
            const uint4* na  = Ab + (size_t)(it + 1) * 512;
            const uint4* nb4 = Bb + (size_t)(it + 1) * 1024;
#pragma unroll
            for (int i = 0; i < 2; i++)
                cp_async16(&sA[nbuf * 512 + tid + i * 256], na + tid + i * 256);
#pragma unroll
            for (int i = 0; i < 4; i++)
                cp_async16(&sB[nbuf * 1024 + tid + i * 256], nb4 + tid + i * 256);
            cp_commit();
            cp_wait<1>();
        } else {
            cp_wait<0>();
        }
        __syncthreads();

        const uint4* bA = sA + buf * 512;
        const uint4* bB = sB + buf * 1024;

#pragma unroll
        for (int ks = 0; ks < 2; ks++) {
            uint4 ah[4], bbv[4];
#pragma unroll
            for (int mi = 0; mi < 4; mi++)
                ah[mi] = bA[(ks * 8 + warp_m * 4 + mi) * 32 + lane];
#pragma unroll
            for (int ni = 0; ni < 4; ni++)
                bbv[ni] = bB[(ks * 16 + warp_n * 4 + ni) * 32 + lane];
#pragma unroll
            for (int mi = 0; mi < 4; mi++) {
                const uint32_t* ap = (const uint32_t*)&ah[mi];
#pragma unroll
                for (int ni = 0; ni < 4; ni++) {
                    uint32_t bfr[2] = {bbv[ni].x, bbv[ni].y};
                    uint32_t bfl[2] = {bbv[ni].z, bbv[ni].w};
                    mma_f16(acc[mi][ni], ap, bfr);
                    mma_f16(acc[mi][ni], ap, bfl);
                }
            }
        }
        __syncthreads();
    }

    // ---------------- epilogue ----------------
    const int pos = *seqc;
    const int bm  = mb * 128;
    const int bn  = nb * 128;

#pragma unroll
    for (int mi = 0; mi < 4; mi++) {
        const int row = bm + warp_m * 64 + mi * 16 + (lane >> 2);
        const int b   = row >> 11;
        const int s   = row & 2047;
        const int tile = s >> 6;
        const int loc  = s & 63;
#pragma unroll
        for (int ni = 0; ni < 4; ni++) {
            const int col = bn + warp_n * 32 + ni * 8 + (lane & 3) * 2;
            const float2 bv2 = *(const float2*)&bias[col];
            const float x0 = acc[mi][ni][0] + bv2.x;
            const float x1 = acc[mi][ni][1] + bv2.y;
            const float x2 = acc[mi][ni][2] + bv2.x;
            const float x3 = acc[mi][ni][3] + bv2.y;

            if (nb < 8) {
                // Q: dense fp32
                if (!in_ns(s, pos)) {
                    float2 o = {x0, x1};
                    *(float2*)&g_q[(size_t)row * DMODEL + col] = o;
                }
                if (!in_ns(s + 8, pos)) {
                    float2 o = {x2, x3};
                    *(float2*)&g_q[(size_t)(row + 8) * DMODEL + col] = o;
                }
            } else if (nb < 16) {
                // K frags: element (loc, kc) pairs over dims
                const int kc = col & 63;
                const int h  = (col >> 6) & 15;
                uint32_t* kb32 = (uint32_t*)(g_kfrag +
                    ((size_t)(b * 16 + h) * NKTILES + tile) * 1024);
                __half2 H0h = __floats2half2_rn(x0, x1);
                __half2 H8h = __floats2half2_rn(x2, x3);
                const uint32_t H0 = *(const uint32_t*)&H0h;
                const uint32_t H8 = *(const uint32_t*)&H8h;
                const uint32_t L0 = pack2h(x0 - __low2float(H0h), x1 - __high2float(H0h));
                const uint32_t L8 = pack2h(x2 - __low2float(H8h), x3 - __high2float(H8h));
                const int word  = (kc >> 3) & 1;
                const int slot0 = ((loc >> 3) * 4 + (kc >> 4)) * 32 + (loc & 7) * 4 + ((kc & 7) >> 1);
                if (!in_ns(s, pos))     { kb32[slot0 * 4 + word] = H0; kb32[slot0 * 4 + word + 2] = L0; }
                if (!in_ns(s + 8, pos)) { kb32[(slot0 + 128) * 4 + word] = H8; kb32[(slot0 + 128) * 4 + word + 2] = L8; }
            } else {
                // V frags: element (d, kk) pairs over keys -> shfl transpose
                const int vc = col & 63;
                const int h  = (col >> 6) & 15;
                uint32_t* vb32 = (uint32_t*)(g_vfrag +
                    ((size_t)(b * 16 + h) * NKTILES + tile) * 1024);
                __half2 H0h = __floats2half2_rn(x0, x1);
                __half2 H8h = __floats2half2_rn(x2, x3);
                const uint32_t H0 = *(const uint32_t*)&H0h;
                const uint32_t H8 = *(const uint32_t*)&H8h;
                const uint32_t L0 = pack2h(x0 - __low2float(H0h), x1 - __high2float(H0h));
                const uint32_t L8 = pack2h(x2 - __low2float(H8h), x3 - __high2float(H8h));
                const uint32_t pH0 = __shfl_xor_sync(0xffffffffu, H0, 4);
                const uint32_t pH8 = __shfl_xor_sync(0xffffffffu, H8, 4);
                const uint32_t pL0 = __shfl_xor_sync(0xffffffffu, L0, 4);
                const uint32_t pL8 = __shfl_xor_sync(0xffffffffu, L8, 4);
                if (((lane >> 2) & 1) == 0) {   // even-key owner
#pragma unroll
                    for (int pp = 0; pp < 2; pp++) {
                        const int kl = loc + pp * 8;      // local, even
                        const int kg = s + pp * 8;        // global
                        const uint32_t Ah = pp ? H8 : H0;
                        const uint32_t Bh = pp ? pH8 : pH0;
                        const uint32_t Al = pp ? L8 : L0;
                        const uint32_t Bl = pp ? pL8 : pL0;
                        const bool ok0 = !in_ns(kg, pos);
                        const bool ok1 = !in_ns(kg + 1, pos);
                        const int word = (kl >> 3) & 1;
#pragma unroll
                        for (int dd = 0; dd < 2; dd++) {
                            const int d = vc + dd;
                            const int slot = ((d >> 3) * 4 + (kl >> 4)) * 32 + (d & 7) * 4 + ((kl & 7) >> 1);
                            const uint32_t wh = dd ? __byte_perm(Ah, Bh, 0x7632)
                                                   : __byte_perm(Ah, Bh, 0x5410);
                            const uint32_t wl = dd ? __byte_perm(Al, Bl, 0x7632)
                                                   : __byte_perm(Al, Bl, 0x5410);
                            uint32_t* p = vb32 + slot * 4 + word;
                            if (ok0 && ok1) {
                                p[0] = wh; p[2] = wl;
                            } else {
                                unsigned short* ps = (unsigned short*)p;
                                if (ok0) { ps[0] = (unsigned short)(wh & 0xffff);
                                           ps[4] = (unsigned short)(wl & 0xffff); }
                                if (ok1) { ps[1] = (unsigned short)(wh >> 16);
                                           ps[5] = (unsigned short)(wl >> 16); }
                            }
                        }
                    }
                }
            }
        }
    }
}

// ---------------------------------------------------------------------------
// Output projection frag GEMM (reads actx frags from attention)
// ---------------------------------------------------------------------------
__global__ void __launch_bounds__(256) gemm_out_kernel(
    const float* __restrict__ bias, float* __restrict__ C)
{
    extern __shared__ uint4 dyn[];
    uint4* sA = dyn;
    uint4* sB = dyn + 1024;

    const int tid    = threadIdx.x;
    const int lane   = tid & 31;
    const int wid    = tid >> 5;
    const int nb     = blockIdx.x;
    const int mb     = blockIdx.y;
    const int warp_m = (wid >> 2);
    const int warp_n = (wid & 3);

    const uint4* Ab = g_actx_frag + (size_t)mb * KIT * 512;
    const uint4* Bb = g_wout_frag + (size_t)nb * KIT * 1024;

    float acc[4][4][4];
#pragma unroll
    for (int mi = 0; mi < 4; mi++)
#pragma unroll
        for (int ni = 0; ni < 4; ni++)
#pragma unroll
            for (int r = 0; r < 4; r++) acc[mi][ni][r] = 0.f;

#pragma unroll
    for (int i = 0; i < 2; i++) cp_async16(&sA[tid + i * 256], Ab + tid + i * 256);
#pragma unroll
    for (int i = 0; i < 4; i++) cp_async16(&sB[tid + i * 256], Bb + tid + i * 256);
    cp_commit();

    for (int it = 0; it < KIT; it++) {
        const int buf = it & 1;
        if (it + 1 < KIT) {
            const int nbuf = (it + 1) & 1;
            const uint4* na  = Ab + (size_t)(it + 1) * 512;
            const uint4* nb4 = Bb + (size_t)(it + 1) * 1024;
#pragma unroll
            for (int i = 0; i < 2; i++)
                cp_async16(&sA[nbuf * 512 + tid + i * 256], na + tid + i * 256);
#pragma unroll
            for (int i = 0; i < 4; i++)
                cp_async16(&sB[nbuf * 1024 + tid + i * 256], nb4 + tid + i * 256);
            cp_commit();
            cp_wait<1>();
        } else {
            cp_wait<0>();
        }
        __syncthreads();

        const uint4* bA = sA + buf * 512;
        const uint4* bB = sB + buf * 1024;

#pragma unroll
        for (int ks = 0; ks < 2; ks++) {
            uint4 ah[4], bbv[4];
#pragma unroll
            for (int mi = 0; mi < 4; mi++)
                ah[mi] = bA[(ks * 8 + warp_m * 4 + mi) * 32 + lane];
#pragma unroll
            for (int ni = 0; ni < 4; ni++)
                bbv[ni] = bB[(ks * 16 + warp_n * 4 + ni) * 32 + lane];
#pragma unroll
            for (int mi = 0; mi < 4; mi++) {
                const uint32_t* ap = (const uint32_t*)&ah[mi];
#pragma unroll
                for (int ni = 0; ni < 4; ni++) {
                    uint32_t bfr[2] = {bbv[ni].x, bbv[ni].y};
                    uint32_t bfl[2] = {bbv[ni].z, bbv[ni].w};
                    mma_f16(acc[mi][ni], ap, bfr);
                    mma_f16(acc[mi][ni], ap, bfl);
                }
            }
        }
        __syncthreads();
    }

    const int bm = mb * 128;
    const int bn = nb * 128;
#pragma unroll
    for (int mi = 0; mi < 4; mi++) {
        const int row = bm + warp_m * 64 + mi * 16 + (lane >> 2);
#pragma unroll
        for (int ni = 0; ni < 4; ni++) {
            const int col = bn + warp_n * 32 + ni * 8 + (lane & 3) * 2;
            const float2 bv2 = *(const float2*)&bias[col];
            float2 o0, o1;
            o0.x = acc[mi][ni][0] + bv2.x;  o0.y = acc[mi][ni][1] + bv2.y;
            o1.x = acc[mi][ni][2] + bv2.x;  o1.y = acc[mi][ni][3] + bv2.y;
            *(float2*)&C[(size_t)row * DMODEL + col]       = o0;
            *(float2*)&C[(size_t)(row + 8) * DMODEL + col] = o1;
        }
    }
}

// ---------------------------------------------------------------------------
// Tensor-core flash attention (R9, Q reads from dense g_q)
// ---------------------------------------------------------------------------
__global__ void __launch_bounds__(256, 2) attn_tc_kernel(
    const unsigned int* __restrict__ mask)
{
    extern __shared__ uint4 dyn[];
    uint4*    sK    = dyn;
    uint4*    sV    = dyn + 2048;
    uint32_t* sMask = (uint32_t*)(dyn + 4096);

    const int tid  = threadIdx.x;
    const int w    = tid >> 5;
    const int lane = tid & 31;
    const int bxr  = (S_LEN / 128 - 1) - blockIdx.x;
    const int bh   = blockIdx.y;
    const int b    = bh >> 4;
    const int h    = bh & 15;
    const int r0   = bxr * 128;

    const float* qb = g_q + ((size_t)b * S_LEN) * DMODEL + h * HDIM;
    const unsigned int* mb = mask + b * S_LEN;
    const uint4* kfb = g_kfrag + ((size_t)bh * NKTILES << 10);
    const uint4* vfb = g_vfrag + ((size_t)bh * NKTILES << 10);

    const int ntiles = (r0 + 128) >> 6;

    uint32_t qh[4][4];
    {
        const int rlo = r0 + w * 16 + (lane >> 2);
        const float* q0 = qb + (size_t)rlo * DMODEL;
        const float* q1 = qb + (size_t)(rlo + 8) * DMODEL;
#pragma unroll
        for (int ks = 0; ks < 4; ks++) {
            const int c = ks * 16 + (lane & 3) * 2;
            float2 x0 = *(const float2*)&q0[c];
            float2 x1 = *(const float2*)&q1[c];
            float2 x2 = *(const float2*)&q0[c + 8];
            float2 x3 = *(const float2*)&q1[c + 8];
            qh[ks][0] = pack2h(x0.x * 0.125f, x0.y * 0.125f);
            qh[ks][1] = pack2h(x1.x * 0.125f, x1.y * 0.125f);
            qh[ks][2] = pack2h(x2.x * 0.125f, x2.y * 0.125f);
            qh[ks][3] = pack2h(x3.x * 0.125f, x3.y * 0.125f);
        }
    }

    float m_i[2] = {-1e30f, -1e30f};
    float l_i[2] = {0.f, 0.f};
    float o_acc[8][4];
#pragma unroll
    for (int dt = 0; dt < 8; dt++)
#pragma unroll
        for (int r = 0; r < 4; r++) o_acc[dt][r] = 0.f;

    const int q0g = r0 + w * 16 + (lane >> 2);

    {
#pragma unroll
        for (int i = 0; i < 4; i++) {
            const int idx = tid + i * 256;
            cp_async16(&sK[idx], kfb + idx);
            cp_async16(&sV[idx], vfb + idx);
        }
        if (tid < 16) cp_async16(&sMask[tid * 4], mb + tid * 4);
        cp_commit();
    }

    for (int t = 0; t < ntiles; t++) {
        const int buf = t & 1;
        if (t + 1 < ntiles) {
            const int nb = (t + 1) & 1;
            const uint4* srcK = kfb + ((size_t)(t + 1) << 10);
            const uint4* srcV = vfb + ((size_t)(t + 1) << 10);
#pragma unroll
            for (int i = 0; i < 4; i++) {
                const int idx = tid + i * 256;
                cp_async16(&sK[nb * 1024 + idx], srcK + idx);
                cp_async16(&sV[nb * 1024 + idx], srcV + idx);
            }
            if (tid < 16) cp_async16(&sMask[nb * 64 + tid * 4], mb + (t + 1) * 64 + tid * 4);
            cp_commit();
            cp_wait<1>();
        } else {
            cp_wait<0>();
        }
        __syncthreads();

        const int k0 = t << 6;
        const uint4* bK = sK + buf * 1024;
        const uint4* bV = sV + buf * 1024;
        const uint32_t* bM = sMask + buf * 64;

        float s[8][4];
#pragma unroll
        for (int nt = 0; nt < 8; nt++)
#pragma unroll
            for (int r = 0; r < 4; r++) s[nt][r] = 0.f;

#pragma unroll
        for (int ks = 0; ks < 4; ks++) {
#pragma unroll
            for (int nt = 0; nt < 8; nt++) {
                const uint4 v = bK[(nt * 4 + ks) * 32 + lane];
                uint32_t bfr[2] = {v.x, v.y};
                uint32_t bfl[2] = {v.z, v.w};
                mma_f16(s[nt], qh[ks], bfr);
                mma_f16(s[nt], qh[ks], bfl);
            }
        }

#pragma unroll
        for (int row = 0; row < 2; row++) {
            const int qg = q0g + row * 8;
            float mx = -1e30f;
#pragma unroll
            for (int nt = 0; nt < 8; nt++)
#pragma unroll
                for (int c = 0; c < 2; c++) {
                    const int idx = row * 2 + c;
                    const int kl  = nt * 8 + (lane & 3) * 2 + c;
                    const bool ok = (bM[kl] != 0u) && (k0 + kl <= qg);
                    s[nt][idx] = ok ? s[nt][idx] : -1e9f;
                    mx = fmaxf(mx, s[nt][idx]);
                }
            mx = fmaxf(mx, __shfl_xor_sync(0xffffffffu, mx, 1));
            mx = fmaxf(mx, __shfl_xor_sync(0xffffffffu, mx, 2));
            const float mnew = fmaxf(m_i[row], mx);
            const float corr = __expf(m_i[row] - mnew);
            float sum = 0.f;
#pragma unroll
            for (int nt = 0; nt < 8; nt++)
#pragma unroll
                for (int c = 0; c < 2; c++) {
                    const int idx = row * 2 + c;
                    const float p = __expf(s[nt][idx] - mnew);
                    s[nt][idx] = p;
                    sum += p;
                }
            sum += __shfl_xor_sync(0xffffffffu, sum, 1);
            sum += __shfl_xor_sync(0xffffffffu, sum, 2);
            l_i[row] = l_i[row] * corr + sum;
            m_i[row] = mnew;
#pragma unroll
            for (int dt = 0; dt < 8; dt++) {
                o_acc[dt][row * 2 + 0] *= corr;
                o_acc[dt][row * 2 + 1] *= corr;
            }
        }

#pragma unroll
        for (int ks2 = 0; ks2 < 4; ks2++) {
            uint32_t pah[4];
            pah[0] = pack2h(s[ks2*2][0],   s[ks2*2][1]);
            pah[1] = pack2h(s[ks2*2][2],   s[ks2*2][3]);
            pah[2] = pack2h(s[ks2*2+1][0], s[ks2*2+1][1]);
            pah[3] = pack2h(s[ks2*2+1][2], s[ks2*2+1][3]);
#pragma unroll
            for (int dt = 0; dt < 8; dt++) {
                const uint4 v = bV[(dt * 4 + ks2) * 32 + lane];
                uint32_t bfr[2] = {v.x, v.y};
                uint32_t bfl[2] = {v.z, v.w};
                mma_f16(o_acc[dt], pah, bfr);
                mma_f16(o_acc[dt], pah, bfl);
            }
        }
        __syncthreads();
    }

    // epilogue: emit ctx A-fragments (fp16)
    const float inv0 = 1.f / l_i[0];
    const float inv1 = 1.f / l_i[1];
    uint4* dst = g_actx_frag + ((size_t)(b * 16 + (r0 >> 7)) * KIT) * 512;
#pragma unroll
    for (int f = 0; f < 4; f++) {
        const int it  = h * 2 + (f >> 1);
        const int ks  = f & 1;
        const int dt0 = f * 2, dt1 = f * 2 + 1;
        uint4 u;
        u.x = pack2h(o_acc[dt0][0] * inv0, o_acc[dt0][1] * inv0);
        u.y = pack2h(o_acc[dt0][2] * inv1, o_acc[dt0][3] * inv1);
        u.z = pack2h(o_acc[dt1][0] * inv0, o_acc[dt1][1] * inv0);
        u.w = pack2h(o_acc[dt1][2] * inv1, o_acc[dt1][3] * inv1);
        dst[(size_t)it * 512 + (ks * 8 + w) * 32 + lane] = u;
    }
}

// ---------------------------------------------------------------------------
extern "C" void kernel_launch(void* const* d_in, const int* in_sizes, int n_in,
                              void* d_out, int out_size)
{
    const float*        tokens = (const float*)d_in[0];
    const unsigned int* mask   = (const unsigned int*)d_in[1];
    const int*          seqc   = (const int*)d_in[2];
    const float*        W_qkv  = (const float*)d_in[3];
    const float*        b_qkv  = (const float*)d_in[4];
    const float*        Wq     = (const float*)d_in[5];
    const float*        bq     = (const float*)d_in[6];
    const float*        Wk     = (const float*)d_in[7];
    const float*        bk     = (const float*)d_in[8];
    const float*        Wv     = (const float*)d_in[9];
    const float*        bv     = (const float*)d_in[10];
    const float*        W_out  = (const float*)d_in[11];
    const float*        b_out  = (const float*)d_in[12];
    float*              out    = (float*)d_out;

    cudaFuncSetAttribute(attn_tc_kernel,
                         cudaFuncAttributeMaxDynamicSharedMemorySize, 66048);
    cudaFuncSetAttribute(gemm_qkv_kernel,
                         cudaFuncAttributeMaxDynamicSharedMemorySize, 49152);
    cudaFuncSetAttribute(gemm_out_kernel,
                         cudaFuncAttributeMaxDynamicSharedMemorySize, 49152);

    // 1) all operand presplits (one kernel)
    presplit_all_kernel<<<2048, 256>>>(tokens, W_qkv, W_out);

    // 2) QKV projection + fused K/V frag emission + fused ns blocks
    gemm_qkv_kernel<<<816, 256, 49152>>>(b_qkv, tokens, seqc,
                                         Wq, bq, Wk, bk, Wv, bv);

    // 3) attention (emits ctx A-fragments)
    dim3 g2(S_LEN / 128, BATCH * NHEADS);
    attn_tc_kernel<<<g2, 256, 66048>>>(mask);

    // 4) output projection -> d_out
    dim3 g3(DMODEL / 128, MBLK);
    gemm_out_kernel<<<g3, 256, 49152>>>(b_out, out);
}